// round 4
// baseline (speedup 1.0000x reference)
#include <cuda_runtime.h>
#include <math.h>

#define NLAYER 8
#define HH 4
#define DD 64
#define QKD 64
#define VDIM 128
#define TT 17
#define FFND 12

// ---------------- precomputed tables (rotary + decay mask) ----------------
__device__ float g_sin[TT][16];
__device__ float g_cos[TT][16];
__device__ float g_dmask[HH][TT][TT];

__global__ void init_tables_kernel() {
  if (threadIdx.x != 0 || blockIdx.x != 0) return;
  double angle[16];
  for (int u = 0; u < 8; ++u) {
    double a = pow(10000.0, -(double)u / 7.0);
    angle[2 * u] = a;
    angle[2 * u + 1] = a;
  }
  for (int t = 0; t < TT; ++t)
    for (int d2 = 0; d2 < 16; ++d2) {
      g_sin[t][d2] = (float)sin((double)t * angle[d2]);
      g_cos[t][d2] = (float)cos((double)t * angle[d2]);
    }
  double l0 = log(1.0 / 32.0), l1 = log(1.0 / 512.0);
  for (int h = 0; h < HH; ++h) {
    double gamma = 1.0 - exp(l0 + (double)h * (l1 - l0) / 3.0);
    for (int n = 0; n < TT; ++n) {
      double vals[TT];
      double rs = 0.0;
      for (int m = 0; m < TT; ++m) {
        double v_ = 0.0;
        if (n >= m) v_ = pow(gamma, (double)(n - m));
        vals[m] = v_;
        rs += v_;
      }
      double inv = 1.0 / sqrt(rs);
      for (int m = 0; m < TT; ++m) g_dmask[h][n][m] = (float)(vals[m] * inv);
    }
  }
}

// ---------------- shared memory ----------------
struct Smem {
  float h[TT][68];
  float xl[TT][68];
  float q[TT][68];
  float k[TT][68];
  float v[TT][132];
  float g[TT][132];
  float s[HH][TT][18];
  float o[TT][132];
  float f[TT][FFND];
  float sin_[TT][16], cos_[TT][16];
  float mu[TT], rs[TT];
  float gmu[HH][TT], grs[HH][TT];
  float inv_[HH][TT];
  float z[16];
};
union SmemU {
  Smem a;
  float img[3 * 32 * 32];
};

__global__ __launch_bounds__(64) void vit_kernel(
    const float* __restrict__ x, const float* __restrict__ patch_w,
    const float* __restrict__ patch_b, const float* __restrict__ cls,
    const float* __restrict__ pos, const float* __restrict__ Wq,
    const float* __restrict__ Wk, const float* __restrict__ Wv,
    const float* __restrict__ Wg, const float* __restrict__ Wo,
    const float* __restrict__ ln1_s, const float* __restrict__ ln1_b,
    const float* __restrict__ w1, const float* __restrict__ b1,
    const float* __restrict__ w2, const float* __restrict__ b2,
    const float* __restrict__ ln2_s, const float* __restrict__ ln2_b,
    const float* __restrict__ lnf_s, const float* __restrict__ lnf_b,
    const float* __restrict__ neck_w, const float* __restrict__ neck_b,
    const float* __restrict__ head_w, const float* __restrict__ head_b,
    float* __restrict__ out) {
  extern __shared__ char smem_raw[];
  SmemU& U = *reinterpret_cast<SmemU*>(smem_raw);
  Smem& S = U.a;

  const int b = blockIdx.x;
  const int d = threadIdx.x;  // 0..63

  const float* xb = x + (size_t)b * 3072;
  for (int i = d; i < 3072; i += 64) U.img[i] = xb[i];
  __syncthreads();

  // ---------------- patch embedding + cls + pos ----------------
  float tokcol[TT];
  for (int t = 1; t < TT; ++t) {
    int p = t - 1, pr = p >> 2, pc = p & 3;
    float acc = patch_b[d] + pos[t * DD + d];
    for (int c = 0; c < 3; ++c) {
#pragma unroll
      for (int i2 = 0; i2 < 8; ++i2) {
        const float* row = &U.img[c * 1024 + (pr * 8 + i2) * 32 + pc * 8];
        const float* wrow = &patch_w[(c * 64 + i2 * 8) * DD + d];
#pragma unroll
        for (int j = 0; j < 8; ++j) acc += row[j] * wrow[j * DD];
      }
    }
    tokcol[t] = acc;
  }
  tokcol[0] = cls[d] + pos[d];
  __syncthreads();  // img reads done; S.* may now be written
#pragma unroll
  for (int t = 0; t < TT; ++t) S.h[t][d] = tokcol[t];
  for (int i = d; i < TT * 16; i += 64) {
    (&S.sin_[0][0])[i] = (&g_sin[0][0])[i];
    (&S.cos_[0][0])[i] = (&g_cos[0][0])[i];
  }
  __syncthreads();

  const float sgn = (d & 1) ? 1.f : -1.f;
  const int dim = d & 15;
  const int h0 = d >> 5, h1 = 2 + (d >> 5);

  // ---------------- transformer layers ----------------
  for (int L = 0; L < NLAYER; ++L) {
    // --- ln1 ---
    if (d < TT) {
      float s1 = 0.f;
      for (int e = 0; e < DD; ++e) s1 += S.h[d][e];
      float mu = s1 * (1.f / DD);
      float s2 = 0.f;
      for (int e = 0; e < DD; ++e) {
        float dv = S.h[d][e] - mu;
        s2 += dv * dv;
      }
      S.mu[d] = mu;
      S.rs[d] = 1.f / sqrtf(s2 * (1.f / DD) + 1e-5f);
    }
    __syncthreads();
    {
      float sc = ln1_s[L * DD + d], bi = ln1_b[L * DD + d];
#pragma unroll
      for (int t = 0; t < TT; ++t)
        S.xl[t][d] = (S.h[t][d] - S.mu[t]) * S.rs[t] * sc + bi;
    }
    __syncthreads();

    // --- q,k projection + rotary via register shuffle ---
    {
      float qa[TT], ka[TT];
#pragma unroll
      for (int t = 0; t < TT; ++t) { qa[t] = 0.f; ka[t] = 0.f; }
      const float* Wq_ = Wq + L * DD * QKD;
      const float* Wk_ = Wk + L * DD * QKD;
      for (int e = 0; e < DD; ++e) {
        float wq = Wq_[e * QKD + d], wk = Wk_[e * QKD + d];
#pragma unroll
        for (int t = 0; t < TT; ++t) {
          float xv = S.xl[t][e];
          qa[t] += xv * wq;
          ka[t] += xv * wk;
        }
      }
#pragma unroll
      for (int t = 0; t < TT; ++t) {
        float qn = __shfl_xor_sync(0xffffffffu, qa[t], 1);
        float kn = __shfl_xor_sync(0xffffffffu, ka[t], 1);
        float cs = S.cos_[t][dim], sn = S.sin_[t][dim];
        S.q[t][d] = qa[t] * cs + sgn * qn * sn;
        S.k[t][d] = (ka[t] * cs + sgn * kn * sn) * 0.25f;
      }
    }
    __syncthreads();

    // --- v,g projections (cols d, d+64) ---
    {
      float va[TT], vb[TT], ga[TT], gb[TT];
#pragma unroll
      for (int t = 0; t < TT; ++t) { va[t] = vb[t] = ga[t] = gb[t] = 0.f; }
      const float* Wv_ = Wv + L * DD * VDIM;
      const float* Wg_ = Wg + L * DD * VDIM;
      for (int e = 0; e < DD; ++e) {
        float wv0 = Wv_[e * VDIM + d], wv1 = Wv_[e * VDIM + 64 + d];
        float wg0 = Wg_[e * VDIM + d], wg1 = Wg_[e * VDIM + 64 + d];
#pragma unroll
        for (int t = 0; t < TT; ++t) {
          float xv = S.xl[t][e];
          va[t] += xv * wv0;
          vb[t] += xv * wv1;
          ga[t] += xv * wg0;
          gb[t] += xv * wg1;
        }
      }
#pragma unroll
      for (int t = 0; t < TT; ++t) {
        S.v[t][d] = va[t];
        S.v[t][64 + d] = vb[t];
        S.g[t][d] = ga[t];
        S.g[t][64 + d] = gb[t];
      }
    }
    __syncthreads();

    // --- scores = (q·k) * dmask ---
    for (int idx = d; idx < HH * TT * TT; idx += 64) {
      int hh = idx / (TT * TT);
      int r = idx - hh * TT * TT;
      int n = r / TT, m = r - n * TT;
      float sv = 0.f;
#pragma unroll
      for (int e = 0; e < 16; ++e)
        sv += S.q[n][hh * 16 + e] * S.k[m][hh * 16 + e];
      S.s[hh][n][m] = sv * g_dmask[hh][n][m];
    }
    __syncthreads();
    // --- denominator: 68 (head,token) pairs on 64 threads -> strided! ---
    for (int idx = d; idx < HH * TT; idx += 64) {
      int hh = idx / TT, n = idx - hh * TT;
      float sv = 0.f;
      for (int m = 0; m < TT; ++m) sv += S.s[hh][n][m];
      S.inv_[hh][n] = 1.f / fmaxf(fabsf(sv), 1.f);
    }
    __syncthreads();

    // --- o = (s @ v) / denom ---
    float o0[TT], o1[TT];
#pragma unroll
    for (int n = 0; n < TT; ++n) { o0[n] = 0.f; o1[n] = 0.f; }
    for (int m = 0; m < TT; ++m) {
      float v0 = S.v[m][d], v1 = S.v[m][64 + d];
#pragma unroll
      for (int n = 0; n < TT; ++n) {
        o0[n] += S.s[h0][n][m] * v0;
        o1[n] += S.s[h1][n][m] * v1;
      }
    }
#pragma unroll
    for (int n = 0; n < TT; ++n) {
      o0[n] *= S.inv_[h0][n];
      o1[n] *= S.inv_[h1][n];
      S.o[n][d] = o0[n];
      S.o[n][64 + d] = o1[n];
    }
    __syncthreads();
    // --- group norm: 68 (head,token) pairs on 64 threads -> strided! ---
    for (int idx = d; idx < HH * TT; idx += 64) {
      int hh = idx / TT, n = idx - hh * TT;
      float s1 = 0.f;
      for (int e = 0; e < 32; ++e) s1 += S.o[n][hh * 32 + e];
      float mu = s1 * (1.f / 32);
      float s2 = 0.f;
      for (int e = 0; e < 32; ++e) {
        float dv = S.o[n][hh * 32 + e] - mu;
        s2 += dv * dv;
      }
      S.gmu[hh][n] = mu;
      S.grs[hh][n] = 1.f / sqrtf(s2 * (1.f / 32) + 1e-5f);
    }
    __syncthreads();
    // --- a = silu(g) * gnorm(o) ---
#pragma unroll
    for (int n = 0; n < TT; ++n) {
      float g0 = S.g[n][d], g1 = S.g[n][64 + d];
      float sg0 = g0 / (1.f + expf(-g0));
      float sg1 = g1 / (1.f + expf(-g1));
      S.g[n][d] = sg0 * (o0[n] - S.gmu[h0][n]) * S.grs[h0][n];
      S.g[n][64 + d] = sg1 * (o1[n] - S.gmu[h1][n]) * S.grs[h1][n];
    }
    __syncthreads();
    // --- output projection + residual ---
    {
      const float* Wo_ = Wo + L * VDIM * DD;
      float rc[TT];
#pragma unroll
      for (int n = 0; n < TT; ++n) rc[n] = 0.f;
      for (int c = 0; c < VDIM; ++c) {
        float w = Wo_[c * DD + d];
#pragma unroll
        for (int n = 0; n < TT; ++n) rc[n] += S.g[n][c] * w;
      }
#pragma unroll
      for (int n = 0; n < TT; ++n) S.h[n][d] += rc[n];
    }
    __syncthreads();

    // --- ln2 ---
    if (d < TT) {
      float s1 = 0.f;
      for (int e = 0; e < DD; ++e) s1 += S.h[d][e];
      float mu = s1 * (1.f / DD);
      float s2 = 0.f;
      for (int e = 0; e < DD; ++e) {
        float dv = S.h[d][e] - mu;
        s2 += dv * dv;
      }
      S.mu[d] = mu;
      S.rs[d] = 1.f / sqrtf(s2 * (1.f / DD) + 1e-5f);
    }
    __syncthreads();
    {
      float sc = ln2_s[L * DD + d], bi = ln2_b[L * DD + d];
#pragma unroll
      for (int t = 0; t < TT; ++t)
        S.xl[t][d] = (S.h[t][d] - S.mu[t]) * S.rs[t] * sc + bi;
    }
    __syncthreads();
    // --- FFN fc1 + gelu(tanh) ---
    for (int idx = d; idx < TT * FFND; idx += 64) {
      int n = idx / FFND, j = idx - n * FFND;
      float acc = b1[L * FFND + j];
      for (int e = 0; e < DD; ++e)
        acc += S.xl[n][e] * w1[(L * DD + e) * FFND + j];
      float c3 = acc * acc * acc;
      S.f[n][j] = 0.5f * acc *
                  (1.f + tanhf(0.7978845608028654f * (acc + 0.044715f * c3)));
    }
    __syncthreads();
    // --- FFN fc2 + residual ---
    {
      float bb = b2[L * DD + d];
#pragma unroll
      for (int n = 0; n < TT; ++n) {
        float acc = bb;
#pragma unroll
        for (int j = 0; j < FFND; ++j)
          acc += S.f[n][j] * w2[(L * FFND + j) * DD + d];
        S.h[n][d] += acc;
      }
    }
    __syncthreads();
  }

  // ---------------- final LN (token 16) + neck + head ----------------
  if (d == 0) {
    float s1 = 0.f;
    for (int e = 0; e < DD; ++e) s1 += S.h[16][e];
    float mu = s1 * (1.f / DD);
    float s2 = 0.f;
    for (int e = 0; e < DD; ++e) {
      float dv = S.h[16][e] - mu;
      s2 += dv * dv;
    }
    S.mu[0] = mu;
    S.rs[0] = 1.f / sqrtf(s2 * (1.f / DD) + 1e-5f);
  }
  __syncthreads();
  S.xl[0][d] = (S.h[16][d] - S.mu[0]) * S.rs[0] * lnf_s[d] + lnf_b[d];
  __syncthreads();
  if (d < 16) {
    float acc = neck_b[d];
    for (int e = 0; e < DD; ++e) acc += S.xl[0][e] * neck_w[e * 16 + d];
    S.z[d] = acc;
  }
  __syncthreads();
  if (d < 10) {
    float acc = head_b[d];
#pragma unroll
    for (int uu = 0; uu < 16; ++uu) acc += S.z[uu] * head_w[uu * 10 + d];
    out[(size_t)b * 10 + d] = acc;
  }
}

extern "C" void kernel_launch(void* const* d_in, const int* in_sizes, int n_in,
                              void* d_out, int out_size) {
  const float* x = (const float*)d_in[0];
  const float* patch_w = (const float*)d_in[1];
  const float* patch_b = (const float*)d_in[2];
  const float* cls = (const float*)d_in[3];
  const float* pos = (const float*)d_in[4];
  const float* Wq = (const float*)d_in[5];
  const float* Wk = (const float*)d_in[6];
  const float* Wv = (const float*)d_in[7];
  const float* Wg = (const float*)d_in[8];
  const float* Wo = (const float*)d_in[9];
  const float* ln1_s = (const float*)d_in[10];
  const float* ln1_b = (const float*)d_in[11];
  const float* w1 = (const float*)d_in[12];
  const float* b1 = (const float*)d_in[13];
  const float* w2 = (const float*)d_in[14];
  const float* b2 = (const float*)d_in[15];
  const float* ln2_s = (const float*)d_in[16];
  const float* ln2_b = (const float*)d_in[17];
  const float* lnf_s = (const float*)d_in[18];
  const float* lnf_b = (const float*)d_in[19];
  const float* neck_w = (const float*)d_in[20];
  const float* neck_b = (const float*)d_in[21];
  const float* head_w = (const float*)d_in[22];
  const float* head_b = (const float*)d_in[23];
  float* out = (float*)d_out;

  int B = in_sizes[0] / 3072;
  size_t smem_bytes = sizeof(SmemU);
  cudaFuncSetAttribute(vit_kernel, cudaFuncAttributeMaxDynamicSharedMemorySize,
                       (int)smem_bytes);

  init_tables_kernel<<<1, 1>>>();
  vit_kernel<<<B, 64, smem_bytes>>>(x, patch_w, patch_b, cls, pos, Wq, Wk, Wv,
                                    Wg, Wo, ln1_s, ln1_b, w1, b1, w2, b2, ln2_s,
                                    ln2_b, lnf_s, lnf_b, neck_w, neck_b, head_w,
                                    head_b, out);
}

// round 7
// speedup vs baseline: 1.1468x; 1.1468x over previous
#include <cuda_runtime.h>
#include <math.h>

#define NLAYER 8
#define HH 4
#define DD 64
#define QKD 64
#define VDIM 128
#define TT 17
#define FFND 12

// ---------------- precomputed tables (rotary + decay mask) ----------------
__device__ float g_sin[TT][16];
__device__ float g_cos[TT][16];
__device__ float g_dmask[HH][TT][TT];

__global__ void init_tables_kernel() {
  if (threadIdx.x != 0 || blockIdx.x != 0) return;
  double angle[16];
  for (int u = 0; u < 8; ++u) {
    double a = pow(10000.0, -(double)u / 7.0);
    angle[2 * u] = a;
    angle[2 * u + 1] = a;
  }
  for (int t = 0; t < TT; ++t)
    for (int d2 = 0; d2 < 16; ++d2) {
      g_sin[t][d2] = (float)sin((double)t * angle[d2]);
      g_cos[t][d2] = (float)cos((double)t * angle[d2]);
    }
  double l0 = log(1.0 / 32.0), l1 = log(1.0 / 512.0);
  for (int h = 0; h < HH; ++h) {
    double gamma = 1.0 - exp(l0 + (double)h * (l1 - l0) / 3.0);
    for (int n = 0; n < TT; ++n) {
      double vals[TT];
      double rs = 0.0;
      for (int m = 0; m < TT; ++m) {
        double v_ = 0.0;
        if (n >= m) v_ = pow(gamma, (double)(n - m));
        vals[m] = v_;
        rs += v_;
      }
      double inv = 1.0 / sqrt(rs);
      for (int m = 0; m < TT; ++m) g_dmask[h][n][m] = (float)(vals[m] * inv);
    }
  }
}

// ---------------- shared memory ----------------
struct SmemQX {
  float xl[TT][68];
  float q[TT][68];
};
union OverQ {
  SmemQX a;
  float o[TT][132];  // overlays xl+q: both dead when o is live
};
struct Smem {
  OverQ oq;
  float h[TT][68];
  float k[TT][68];
  float v[TT][132];
  float g[TT][132];
  float s[HH][TT][18];
  float f[TT][FFND];
  float sin_[TT][16], cos_[TT][16];
  float mu[TT], rs[TT];
  float gmu[HH][TT], grs[HH][TT];
  float inv_[HH][TT];
  float z[16];
};
union SmemU {
  Smem a;
  float img[3 * 32 * 32];
};

__global__ __launch_bounds__(128, 4) void vit_kernel(
    const float* __restrict__ x, const float* __restrict__ patch_w,
    const float* __restrict__ patch_b, const float* __restrict__ cls,
    const float* __restrict__ pos, const float* __restrict__ Wq,
    const float* __restrict__ Wk, const float* __restrict__ Wv,
    const float* __restrict__ Wg, const float* __restrict__ Wo,
    const float* __restrict__ ln1_s, const float* __restrict__ ln1_b,
    const float* __restrict__ w1, const float* __restrict__ b1,
    const float* __restrict__ w2, const float* __restrict__ b2,
    const float* __restrict__ ln2_s, const float* __restrict__ ln2_b,
    const float* __restrict__ lnf_s, const float* __restrict__ lnf_b,
    const float* __restrict__ neck_w, const float* __restrict__ neck_b,
    const float* __restrict__ head_w, const float* __restrict__ head_b,
    float* __restrict__ out) {
  extern __shared__ char smem_raw[];
  SmemU& U = *reinterpret_cast<SmemU*>(smem_raw);
  Smem& S = U.a;

  const int b = blockIdx.x;
  const int d = threadIdx.x;   // 0..127
  const int half = d >> 6;     // 0: q-side, 1: k-side
  const int ch = d & 63;       // column within 64

  const float* xb = x + (size_t)b * 3072;
  for (int i = d; i < 3072; i += 128) U.img[i] = xb[i];
  __syncthreads();

  // ---------------- patch embedding (token-split across halves) ----------
  float tokcol[8];
  const int pt0 = half ? 9 : 1;  // half0: tokens 1..8, half1: tokens 9..16
  for (int i = 0; i < 8; ++i) {
    int t = pt0 + i;
    int p = t - 1, pr = p >> 2, pc = p & 3;
    float acc = patch_b[ch] + pos[t * DD + ch];
    for (int c = 0; c < 3; ++c) {
#pragma unroll
      for (int i2 = 0; i2 < 8; ++i2) {
        const float* row = &U.img[c * 1024 + (pr * 8 + i2) * 32 + pc * 8];
        const float* wrow = &patch_w[(c * 64 + i2 * 8) * DD + ch];
#pragma unroll
        for (int j = 0; j < 8; ++j) acc += row[j] * wrow[j * DD];
      }
    }
    tokcol[i] = acc;
  }
  __syncthreads();  // img reads complete before S.* writes
#pragma unroll
  for (int i = 0; i < 8; ++i) S.h[pt0 + i][ch] = tokcol[i];
  if (half == 0) S.h[0][ch] = cls[ch] + pos[ch];
  for (int i = d; i < TT * 16; i += 128) {
    (&S.sin_[0][0])[i] = (&g_sin[0][0])[i];
    (&S.cos_[0][0])[i] = (&g_cos[0][0])[i];
  }
  __syncthreads();

  const float sgn = (ch & 1) ? 1.f : -1.f;
  const int dim = ch & 15;
  const int hh = d >> 5;         // head for the v/o column this thread owns
  const int tbeg = half ? 9 : 0; // token ranges for split stages
  const int tcnt = half ? 8 : 9;

  // ---------------- transformer layers ----------------
  for (int L = 0; L < NLAYER; ++L) {
    // --- ln1 stats (one token per thread, 17 threads) ---
    if (d < TT) {
      float s1 = 0.f;
      for (int e = 0; e < DD; ++e) s1 += S.h[d][e];
      float mu = s1 * (1.f / DD);
      float s2 = 0.f;
      for (int e = 0; e < DD; ++e) {
        float dv = S.h[d][e] - mu;
        s2 += dv * dv;
      }
      S.mu[d] = mu;
      S.rs[d] = 1.f / sqrtf(s2 * (1.f / DD) + 1e-5f);
    }
    __syncthreads();
    {
      float sc = ln1_s[L * DD + ch], bi = ln1_b[L * DD + ch];
#pragma unroll 9
      for (int i = 0; i < 9; ++i)
        if (i < tcnt) {
          int t = tbeg + i;
          S.oq.a.xl[t][ch] = (S.h[t][ch] - S.mu[t]) * S.rs[t] * sc + bi;
        }
    }
    __syncthreads();

    // --- fused QKVG projection ---
    // thread d: (q col ch | k col ch) + v col d + g col d
    {
      float a0[TT], av[TT], ag[TT];
#pragma unroll
      for (int t = 0; t < TT; ++t) { a0[t] = 0.f; av[t] = 0.f; ag[t] = 0.f; }
      const float* W0 =
          (half ? (Wk + L * DD * QKD) : (Wq + L * DD * QKD));
      const float* Wv_ = Wv + L * DD * VDIM;
      const float* Wg_ = Wg + L * DD * VDIM;
      for (int e = 0; e < DD; ++e) {
        float w0 = W0[e * QKD + ch];
        float wv = Wv_[e * VDIM + d];
        float wg = Wg_[e * VDIM + d];
#pragma unroll
        for (int t = 0; t < TT; ++t) {
          float xv = S.oq.a.xl[t][e];
          a0[t] += xv * w0;
          av[t] += xv * wv;
          ag[t] += xv * wg;
        }
      }
      // rotary on a0 (q for half0, k for half1) via register shuffle
#pragma unroll
      for (int t = 0; t < TT; ++t) {
        float an = __shfl_xor_sync(0xffffffffu, a0[t], 1);
        float cs = S.cos_[t][dim], sn = S.sin_[t][dim];
        float r = a0[t] * cs + sgn * an * sn;
        if (half == 0)
          S.oq.a.q[t][ch] = r;
        else
          S.k[t][ch] = r * 0.25f;
        S.v[t][d] = av[t];
        S.g[t][d] = ag[t];
      }
    }
    __syncthreads();

    // --- scores = (q·k) * dmask ---
    for (int idx = d; idx < HH * TT * TT; idx += 128) {
      int hs = idx / (TT * TT);
      int r = idx - hs * TT * TT;
      int n = r / TT, m = r - n * TT;
      float sv = 0.f;
#pragma unroll
      for (int e = 0; e < 16; ++e)
        sv += S.oq.a.q[n][hs * 16 + e] * S.k[m][hs * 16 + e];
      S.s[hs][n][m] = sv * g_dmask[hs][n][m];
    }
    __syncthreads();
    // --- denominator (68 pairs, 128 threads) ---
    if (d < HH * TT) {
      int hs = d / TT, n = d - hs * TT;
      float sv = 0.f;
      for (int m = 0; m < TT; ++m) sv += S.s[hs][n][m];
      S.inv_[hs][n] = 1.f / fmaxf(fabsf(sv), 1.f);
    }
    __syncthreads();

    // --- o = (s @ v) / denom : one column per thread ---
    float oc[TT];
#pragma unroll
    for (int n = 0; n < TT; ++n) oc[n] = 0.f;
    for (int m = 0; m < TT; ++m) {
      float vm = S.v[m][d];
#pragma unroll
      for (int n = 0; n < TT; ++n) oc[n] += S.s[hh][n][m] * vm;
    }
#pragma unroll
    for (int n = 0; n < TT; ++n) {
      oc[n] *= S.inv_[hh][n];
      S.oq.o[n][d] = oc[n];  // overlay region: xl,q dead now
    }
    __syncthreads();
    // --- group norm stats (68 pairs) ---
    if (d < HH * TT) {
      int hs = d / TT, n = d - hs * TT;
      float s1 = 0.f;
      for (int e = 0; e < 32; ++e) s1 += S.oq.o[n][hs * 32 + e];
      float mu = s1 * (1.f / 32);
      float s2 = 0.f;
      for (int e = 0; e < 32; ++e) {
        float dv = S.oq.o[n][hs * 32 + e] - mu;
        s2 += dv * dv;
      }
      S.gmu[hs][n] = mu;
      S.grs[hs][n] = 1.f / sqrtf(s2 * (1.f / 32) + 1e-5f);
    }
    __syncthreads();
    // --- a = silu(g) * gnorm(o) (one column per thread) ---
#pragma unroll
    for (int n = 0; n < TT; ++n) {
      float g0 = S.g[n][d];
      float sg0 = g0 / (1.f + expf(-g0));
      S.g[n][d] = sg0 * (oc[n] - S.gmu[hh][n]) * S.grs[hh][n];
    }
    __syncthreads();
    // --- output projection + residual (token-split) ---
    {
      const float* Wo_ = Wo + L * VDIM * DD;
      float rc[9];
#pragma unroll
      for (int i = 0; i < 9; ++i) rc[i] = 0.f;
      for (int c = 0; c < VDIM; ++c) {
        float w = Wo_[c * DD + ch];
#pragma unroll 9
        for (int i = 0; i < 9; ++i)
          if (i < tcnt) rc[i] += S.g[tbeg + i][c] * w;
      }
#pragma unroll 9
      for (int i = 0; i < 9; ++i)
        if (i < tcnt) S.h[tbeg + i][ch] += rc[i];
    }
    __syncthreads();

    // --- ln2 ---
    if (d < TT) {
      float s1 = 0.f;
      for (int e = 0; e < DD; ++e) s1 += S.h[d][e];
      float mu = s1 * (1.f / DD);
      float s2 = 0.f;
      for (int e = 0; e < DD; ++e) {
        float dv = S.h[d][e] - mu;
        s2 += dv * dv;
      }
      S.mu[d] = mu;
      S.rs[d] = 1.f / sqrtf(s2 * (1.f / DD) + 1e-5f);
    }
    __syncthreads();
    {
      float sc = ln2_s[L * DD + ch], bi = ln2_b[L * DD + ch];
#pragma unroll 9
      for (int i = 0; i < 9; ++i)
        if (i < tcnt) {
          int t = tbeg + i;
          S.oq.a.xl[t][ch] = (S.h[t][ch] - S.mu[t]) * S.rs[t] * sc + bi;
        }
    }
    __syncthreads();
    // --- FFN fc1 + gelu(tanh) (204 items, strided) ---
    for (int idx = d; idx < TT * FFND; idx += 128) {
      int n = idx / FFND, j = idx - n * FFND;
      float acc = b1[L * FFND + j];
      for (int e = 0; e < DD; ++e)
        acc += S.oq.a.xl[n][e] * w1[(L * DD + e) * FFND + j];
      float c3 = acc * acc * acc;
      S.f[n][j] = 0.5f * acc *
                  (1.f + tanhf(0.7978845608028654f * (acc + 0.044715f * c3)));
    }
    __syncthreads();
    // --- FFN fc2 + residual (token-split) ---
    {
      float bb = b2[L * DD + ch];
#pragma unroll 9
      for (int i = 0; i < 9; ++i)
        if (i < tcnt) {
          int n = tbeg + i;
          float acc = bb;
#pragma unroll
          for (int j = 0; j < FFND; ++j)
            acc += S.f[n][j] * w2[(L * FFND + j) * DD + ch];
          S.h[n][ch] += acc;
        }
    }
    __syncthreads();
  }

  // ---------------- final LN (token 16) + neck + head ----------------
  if (d == 0) {
    float s1 = 0.f;
    for (int e = 0; e < DD; ++e) s1 += S.h[16][e];
    float mu = s1 * (1.f / DD);
    float s2 = 0.f;
    for (int e = 0; e < DD; ++e) {
      float dv = S.h[16][e] - mu;
      s2 += dv * dv;
    }
    S.mu[0] = mu;
    S.rs[0] = 1.f / sqrtf(s2 * (1.f / DD) + 1e-5f);
  }
  __syncthreads();
  if (d < 64)
    S.oq.a.xl[0][d] =
        (S.h[16][d] - S.mu[0]) * S.rs[0] * lnf_s[d] + lnf_b[d];
  __syncthreads();
  if (d < 16) {
    float acc = neck_b[d];
    for (int e = 0; e < DD; ++e) acc += S.oq.a.xl[0][e] * neck_w[e * 16 + d];
    S.z[d] = acc;
  }
  __syncthreads();
  if (d < 10) {
    float acc = head_b[d];
#pragma unroll
    for (int uu = 0; uu < 16; ++uu) acc += S.z[uu] * head_w[uu * 10 + d];
    out[(size_t)b * 10 + d] = acc;
  }
}

extern "C" void kernel_launch(void* const* d_in, const int* in_sizes, int n_in,
                              void* d_out, int out_size) {
  const float* x = (const float*)d_in[0];
  const float* patch_w = (const float*)d_in[1];
  const float* patch_b = (const float*)d_in[2];
  const float* cls = (const float*)d_in[3];
  const float* pos = (const float*)d_in[4];
  const float* Wq = (const float*)d_in[5];
  const float* Wk = (const float*)d_in[6];
  const float* Wv = (const float*)d_in[7];
  const float* Wg = (const float*)d_in[8];
  const float* Wo = (const float*)d_in[9];
  const float* ln1_s = (const float*)d_in[10];
  const float* ln1_b = (const float*)d_in[11];
  const float* w1 = (const float*)d_in[12];
  const float* b1 = (const float*)d_in[13];
  const float* w2 = (const float*)d_in[14];
  const float* b2 = (const float*)d_in[15];
  const float* ln2_s = (const float*)d_in[16];
  const float* ln2_b = (const float*)d_in[17];
  const float* lnf_s = (const float*)d_in[18];
  const float* lnf_b = (const float*)d_in[19];
  const float* neck_w = (const float*)d_in[20];
  const float* neck_b = (const float*)d_in[21];
  const float* head_w = (const float*)d_in[22];
  const float* head_b = (const float*)d_in[23];
  float* out = (float*)d_out;

  int B = in_sizes[0] / 3072;
  size_t smem_bytes = sizeof(SmemU);
  (void)cudaFuncSetAttribute(
      vit_kernel, cudaFuncAttributeMaxDynamicSharedMemorySize, (int)smem_bytes);

  init_tables_kernel<<<1, 1>>>();
  vit_kernel<<<B, 128, smem_bytes>>>(x, patch_w, patch_b, cls, pos, Wq, Wk, Wv,
                                     Wg, Wo, ln1_s, ln1_b, w1, b1, w2, b2,
                                     ln2_s, ln2_b, lnf_s, lnf_b, neck_w, neck_b,
                                     head_w, head_b, out);
}

// round 8
// speedup vs baseline: 1.6523x; 1.4408x over previous
#include <cuda_runtime.h>
#include <math.h>

#define NLAYER 8
#define HH 4
#define DD 64
#define QKD 64
#define VDIM 128
#define TT 17
#define FFND 12

typedef unsigned long long u64;

// ---------------- f32x2 helpers ----------------
__device__ __forceinline__ u64 ld64(const float* p) {
  return *reinterpret_cast<const u64*>(p);
}
__device__ __forceinline__ u64 pk2(float a, float b) {
  u64 r;
  asm("mov.b64 %0, {%1,%2};" : "=l"(r) : "f"(a), "f"(b));
  return r;
}
__device__ __forceinline__ void up2(u64 v, float& a, float& b) {
  asm("mov.b64 {%0,%1}, %2;" : "=f"(a), "=f"(b) : "l"(v));
}
__device__ __forceinline__ void fma2(u64& d_, u64 a, u64 b) {
  asm("fma.rn.f32x2 %0, %1, %2, %0;" : "+l"(d_) : "l"(a), "l"(b));
}

// ---------------- precomputed tables (rotary + decay mask) ----------------
__device__ float g_sin[TT][16];
__device__ float g_cos[TT][16];
__device__ float g_dmask[HH][TT][TT];

__global__ void init_tables_kernel() {
  if (threadIdx.x != 0 || blockIdx.x != 0) return;
  double angle[16];
  for (int u = 0; u < 8; ++u) {
    double a = pow(10000.0, -(double)u / 7.0);
    angle[2 * u] = a;
    angle[2 * u + 1] = a;
  }
  for (int t = 0; t < TT; ++t)
    for (int d2 = 0; d2 < 16; ++d2) {
      g_sin[t][d2] = (float)sin((double)t * angle[d2]);
      g_cos[t][d2] = (float)cos((double)t * angle[d2]);
    }
  double l0 = log(1.0 / 32.0), l1 = log(1.0 / 512.0);
  for (int h = 0; h < HH; ++h) {
    double gamma = 1.0 - exp(l0 + (double)h * (l1 - l0) / 3.0);
    for (int n = 0; n < TT; ++n) {
      double vals[TT];
      double rs = 0.0;
      for (int m = 0; m < TT; ++m) {
        double v_ = 0.0;
        if (n >= m) v_ = pow(gamma, (double)(n - m));
        vals[m] = v_;
        rs += v_;
      }
      double inv = 1.0 / sqrt(rs);
      for (int m = 0; m < TT; ++m) g_dmask[h][n][m] = (float)(vals[m] * inv);
    }
  }
}

// ---------------- shared memory (all array bases at even float offsets) ----
struct Smem {
  float h[TT][68];       // residual, [token][ch]           off 0    (1156)
  float xlT[DD][18];     // LN output, [ch][token]          off 1156 (1152)
  float q[TT][68];       // post-rotary q [t][e]            off 2308 (1156)
  float k[TT][68];       // post-rotary scaled k            off 3464 (1156)
  float gT[VDIM][18];    // g raw then post-silu, [c][t]    off 4620 (2304)
  float sT[HH][TT][18];  // scores [h][m][n]                off 6924 (1224)
  float f[TT][FFND];     //                                 off 8148 (204)
  float sin_[TT][16], cos_[TT][16];
  float mu[TT], rs[TT];
  float z[16];
};
union SmemU {
  Smem a;
  float img[3 * 32 * 32];
};

__global__ __launch_bounds__(128, 4) void vit_kernel(
    const float* __restrict__ x, const float* __restrict__ patch_w,
    const float* __restrict__ patch_b, const float* __restrict__ cls,
    const float* __restrict__ pos, const float* __restrict__ Wq,
    const float* __restrict__ Wk, const float* __restrict__ Wv,
    const float* __restrict__ Wg, const float* __restrict__ Wo,
    const float* __restrict__ ln1_s, const float* __restrict__ ln1_b,
    const float* __restrict__ w1, const float* __restrict__ b1,
    const float* __restrict__ w2, const float* __restrict__ b2,
    const float* __restrict__ ln2_s, const float* __restrict__ ln2_b,
    const float* __restrict__ lnf_s, const float* __restrict__ lnf_b,
    const float* __restrict__ neck_w, const float* __restrict__ neck_b,
    const float* __restrict__ head_w, const float* __restrict__ head_b,
    float* __restrict__ out) {
  extern __shared__ char smem_raw[];
  SmemU& U = *reinterpret_cast<SmemU*>(smem_raw);
  Smem& S = U.a;

  const int b = blockIdx.x;
  const int d = threadIdx.x;  // 0..127
  const int half = d >> 6;    // 0: q-side, 1: k-side
  const int ch = d & 63;

  const float* xb = x + (size_t)b * 3072;
  for (int i = d; i < 3072; i += 128) U.img[i] = xb[i];
  __syncthreads();

  // ---------------- patch embedding (tokens 1-8 / 9-16 across halves) ----
  float tokcol[8];
  const int pt0 = half ? 9 : 1;
  for (int i = 0; i < 8; ++i) {
    int t = pt0 + i;
    int p = t - 1, pr = p >> 2, pc = p & 3;
    float acc = patch_b[ch] + pos[t * DD + ch];
    for (int c = 0; c < 3; ++c) {
#pragma unroll
      for (int i2 = 0; i2 < 8; ++i2) {
        const float* row = &U.img[c * 1024 + (pr * 8 + i2) * 32 + pc * 8];
        const float* wrow = &patch_w[(c * 64 + i2 * 8) * DD + ch];
#pragma unroll
        for (int j = 0; j < 8; ++j) acc += row[j] * wrow[j * DD];
      }
    }
    tokcol[i] = acc;
  }
  __syncthreads();  // img reads complete before S.* writes
#pragma unroll
  for (int i = 0; i < 8; ++i) S.h[pt0 + i][ch] = tokcol[i];
  if (half == 0) S.h[0][ch] = cls[ch] + pos[ch];
  for (int i = d; i < TT * 16; i += 128) {
    (&S.sin_[0][0])[i] = (&g_sin[0][0])[i];
    (&S.cos_[0][0])[i] = (&g_cos[0][0])[i];
  }
  __syncthreads();

  const float sgn = (ch & 1) ? 1.f : -1.f;
  const int dim = ch & 15;
  const int hh = d >> 5;          // head owned by this warp (v/o column d)
  const int tb = half ? 8 : 0;    // token split: 0-7 | 8-16
  const int tc = half ? 9 : 8;
  const u64 one2 = pk2(1.f, 1.f);

  // ---------------- transformer layers ----------------
  for (int L = 0; L < NLAYER; ++L) {
    // --- ln1 stats ---
    if (d < TT) {
      float s1 = 0.f;
      for (int e = 0; e < DD; ++e) s1 += S.h[d][e];
      float mu = s1 * (1.f / DD);
      float s2 = 0.f;
      for (int e = 0; e < DD; ++e) {
        float dv = S.h[d][e] - mu;
        s2 += dv * dv;
      }
      S.mu[d] = mu;
      S.rs[d] = 1.f / sqrtf(s2 * (1.f / DD) + 1e-5f);
    }
    __syncthreads();
    {
      float sc = ln1_s[L * DD + ch], bi = ln1_b[L * DD + ch];
      for (int i = 0; i < tc; ++i) {
        int t = tb + i;
        S.xlT[ch][t] = (S.h[t][ch] - S.mu[t]) * S.rs[t] * sc + bi;
      }
    }
    __syncthreads();

    // --- fused QKVG projection (f32x2 over token pairs) ---
    float vv[TT];  // v column d, lives until s@v
    {
      u64 a0p[8], avp[8], agp[8];
      float a0s = 0.f, avs = 0.f, ags = 0.f;
#pragma unroll
      for (int i = 0; i < 8; ++i) { a0p[i] = 0; avp[i] = 0; agp[i] = 0; }
      const float* W0 = half ? (Wk + L * DD * QKD) : (Wq + L * DD * QKD);
      const float* Wv_ = Wv + L * DD * VDIM;
      const float* Wg_ = Wg + L * DD * VDIM;
      for (int e = 0; e < DD; ++e) {
        float w0 = W0[e * QKD + ch];
        float wv = Wv_[e * VDIM + d];
        float wg = Wg_[e * VDIM + d];
        u64 w0p = pk2(w0, w0), wvp = pk2(wv, wv), wgp = pk2(wg, wg);
        const float* xr = &S.xlT[e][0];
#pragma unroll
        for (int i = 0; i < 8; ++i) {
          u64 xv = ld64(xr + 2 * i);
          fma2(a0p[i], xv, w0p);
          fma2(avp[i], xv, wvp);
          fma2(agp[i], xv, wgp);
        }
        float xs = xr[16];
        a0s += xs * w0;
        avs += xs * wv;
        ags += xs * wg;
      }
      float qa[TT], gg[TT];
#pragma unroll
      for (int i = 0; i < 8; ++i) {
        up2(a0p[i], qa[2 * i], qa[2 * i + 1]);
        up2(avp[i], vv[2 * i], vv[2 * i + 1]);
        up2(agp[i], gg[2 * i], gg[2 * i + 1]);
      }
      qa[16] = a0s;
      vv[16] = avs;
      gg[16] = ags;
      // rotary via shuffle; write q or k; stash raw g in own gT row
#pragma unroll
      for (int t = 0; t < TT; ++t) {
        float an = __shfl_xor_sync(0xffffffffu, qa[t], 1);
        float cs = S.cos_[t][dim], sn = S.sin_[t][dim];
        float r = qa[t] * cs + sgn * an * sn;
        if (half == 0)
          S.q[t][ch] = r;
        else
          S.k[t][ch] = r * 0.25f;
        S.gT[d][t] = gg[t];
      }
    }
    __syncthreads();

    // --- scores = (q·k)*dmask  (f32x2 over e) -> sT[h][m][n] ---
    for (int idx = d; idx < HH * TT * TT; idx += 128) {
      int hs = idx / (TT * TT);
      int r = idx - hs * TT * TT;
      int n = r / TT, m = r - n * TT;
      u64 acc = 0;
      const float* qr = &S.q[n][hs * 16];
      const float* kr = &S.k[m][hs * 16];
#pragma unroll
      for (int i = 0; i < 8; ++i) fma2(acc, ld64(qr + 2 * i), ld64(kr + 2 * i));
      float lo, hi;
      up2(acc, lo, hi);
      S.sT[hs][m][n] = (lo + hi) * g_dmask[hs][n][m];
    }
    __syncthreads();

    // --- s@v + denominator (packed over n); gnorm via warp shuffles; silu ---
    {
      u64 ocp[8], dsp[8];
      float ocs = 0.f, dss = 0.f;
#pragma unroll
      for (int i = 0; i < 8; ++i) { ocp[i] = 0; dsp[i] = 0; }
      const float* sbase = &S.sT[hh][0][0];
#pragma unroll
      for (int m = 0; m < TT; ++m) {
        float vm = vv[m];
        u64 vmp = pk2(vm, vm);
        const float* sr = sbase + m * 18;
#pragma unroll
        for (int i = 0; i < 8; ++i) {
          u64 sp = ld64(sr + 2 * i);
          fma2(ocp[i], sp, vmp);
          fma2(dsp[i], sp, one2);
        }
        float ss = sr[16];
        ocs += ss * vm;
        dss += ss;
      }
      float oc[TT], ds[TT];
#pragma unroll
      for (int i = 0; i < 8; ++i) {
        up2(ocp[i], oc[2 * i], oc[2 * i + 1]);
        up2(dsp[i], ds[2 * i], ds[2 * i + 1]);
      }
      oc[16] = ocs;
      ds[16] = dss;
#pragma unroll
      for (int n = 0; n < TT; ++n) {
        float o = oc[n] / fmaxf(fabsf(ds[n]), 1.f);
        float s1 = o, s2 = o * o;
#pragma unroll
        for (int off = 16; off; off >>= 1) {
          s1 += __shfl_xor_sync(0xffffffffu, s1, off);
          s2 += __shfl_xor_sync(0xffffffffu, s2, off);
        }
        float mu = s1 * (1.f / 32.f);
        float var = s2 * (1.f / 32.f) - mu * mu;
        float grs = rsqrtf(var + 1e-5f);
        float graw = S.gT[d][n];
        float sg = graw / (1.f + expf(-graw));
        S.gT[d][n] = sg * (o - mu) * grs;  // own row: no cross-thread hazard
      }
    }
    __syncthreads();

    // --- output projection + residual (f32x2 over token pairs) ---
    {
      const float* Wo_ = Wo + L * VDIM * DD;
      u64 rcp[4];
      float rcs = 0.f;
#pragma unroll
      for (int i = 0; i < 4; ++i) rcp[i] = 0;
      for (int c = 0; c < VDIM; ++c) {
        float w = Wo_[c * DD + ch];
        u64 wp = pk2(w, w);
        const float* gr = &S.gT[c][tb];
#pragma unroll
        for (int i = 0; i < 4; ++i) fma2(rcp[i], ld64(gr + 2 * i), wp);
        if (half) rcs += gr[8] * w;  // token 16
      }
#pragma unroll
      for (int i = 0; i < 4; ++i) {
        float a, bq;
        up2(rcp[i], a, bq);
        S.h[tb + 2 * i][ch] += a;
        S.h[tb + 2 * i + 1][ch] += bq;
      }
      if (half) S.h[16][ch] += rcs;
    }
    __syncthreads();

    // --- ln2 stats ---
    if (d < TT) {
      float s1 = 0.f;
      for (int e = 0; e < DD; ++e) s1 += S.h[d][e];
      float mu = s1 * (1.f / DD);
      float s2 = 0.f;
      for (int e = 0; e < DD; ++e) {
        float dv = S.h[d][e] - mu;
        s2 += dv * dv;
      }
      S.mu[d] = mu;
      S.rs[d] = 1.f / sqrtf(s2 * (1.f / DD) + 1e-5f);
    }
    __syncthreads();
    {
      float sc = ln2_s[L * DD + ch], bi = ln2_b[L * DD + ch];
      for (int i = 0; i < tc; ++i) {
        int t = tb + i;
        S.xlT[ch][t] = (S.h[t][ch] - S.mu[t]) * S.rs[t] * sc + bi;
      }
    }
    __syncthreads();
    // --- FFN fc1 + gelu(tanh) ---
    for (int idx = d; idx < TT * FFND; idx += 128) {
      int n = idx / FFND, j = idx - n * FFND;
      float acc = b1[L * FFND + j];
      for (int e = 0; e < DD; ++e)
        acc += S.xlT[e][n] * w1[(L * DD + e) * FFND + j];
      float c3 = acc * acc * acc;
      S.f[n][j] = 0.5f * acc *
                  (1.f + tanhf(0.7978845608028654f * (acc + 0.044715f * c3)));
    }
    __syncthreads();
    // --- FFN fc2 + residual ---
    {
      float bb = b2[L * DD + ch];
      for (int i = 0; i < tc; ++i) {
        int n = tb + i;
        float acc = bb;
#pragma unroll
        for (int j = 0; j < FFND; ++j)
          acc += S.f[n][j] * w2[(L * FFND + j) * DD + ch];
        S.h[n][ch] += acc;
      }
    }
    __syncthreads();
  }

  // ---------------- final LN (token 16) + neck + head ----------------
  if (d == 0) {
    float s1 = 0.f;
    for (int e = 0; e < DD; ++e) s1 += S.h[16][e];
    float mu = s1 * (1.f / DD);
    float s2 = 0.f;
    for (int e = 0; e < DD; ++e) {
      float dv = S.h[16][e] - mu;
      s2 += dv * dv;
    }
    S.mu[0] = mu;
    S.rs[0] = 1.f / sqrtf(s2 * (1.f / DD) + 1e-5f);
  }
  __syncthreads();
  if (d < 64)
    S.xlT[d][0] = (S.h[16][d] - S.mu[0]) * S.rs[0] * lnf_s[d] + lnf_b[d];
  __syncthreads();
  if (d < 16) {
    float acc = neck_b[d];
    for (int e = 0; e < DD; ++e) acc += S.xlT[e][0] * neck_w[e * 16 + d];
    S.z[d] = acc;
  }
  __syncthreads();
  if (d < 10) {
    float acc = head_b[d];
#pragma unroll
    for (int uu = 0; uu < 16; ++uu) acc += S.z[uu] * head_w[uu * 10 + d];
    out[(size_t)b * 10 + d] = acc;
  }
}

extern "C" void kernel_launch(void* const* d_in, const int* in_sizes, int n_in,
                              void* d_out, int out_size) {
  const float* x = (const float*)d_in[0];
  const float* patch_w = (const float*)d_in[1];
  const float* patch_b = (const float*)d_in[2];
  const float* cls = (const float*)d_in[3];
  const float* pos = (const float*)d_in[4];
  const float* Wq = (const float*)d_in[5];
  const float* Wk = (const float*)d_in[6];
  const float* Wv = (const float*)d_in[7];
  const float* Wg = (const float*)d_in[8];
  const float* Wo = (const float*)d_in[9];
  const float* ln1_s = (const float*)d_in[10];
  const float* ln1_b = (const float*)d_in[11];
  const float* w1 = (const float*)d_in[12];
  const float* b1 = (const float*)d_in[13];
  const float* w2 = (const float*)d_in[14];
  const float* b2 = (const float*)d_in[15];
  const float* ln2_s = (const float*)d_in[16];
  const float* ln2_b = (const float*)d_in[17];
  const float* lnf_s = (const float*)d_in[18];
  const float* lnf_b = (const float*)d_in[19];
  const float* neck_w = (const float*)d_in[20];
  const float* neck_b = (const float*)d_in[21];
  const float* head_w = (const float*)d_in[22];
  const float* head_b = (const float*)d_in[23];
  float* out = (float*)d_out;

  int B = in_sizes[0] / 3072;
  size_t smem_bytes = sizeof(SmemU);
  (void)cudaFuncSetAttribute(
      vit_kernel, cudaFuncAttributeMaxDynamicSharedMemorySize, (int)smem_bytes);

  init_tables_kernel<<<1, 1>>>();
  vit_kernel<<<B, 128, smem_bytes>>>(x, patch_w, patch_b, cls, pos, Wq, Wk, Wv,
                                     Wg, Wo, ln1_s, ln1_b, w1, b1, w2, b2,
                                     ln2_s, ln2_b, lnf_s, lnf_b, neck_w, neck_b,
                                     head_w, head_b, out);
}

// round 9
// speedup vs baseline: 1.6639x; 1.0070x over previous
#include <cuda_runtime.h>
#include <math.h>

#define NLAYER 8
#define HH 4
#define DD 64
#define QKD 64
#define VDIM 128
#define TT 17
#define FFND 12

typedef unsigned long long u64;

// ---------------- f32x2 helpers ----------------
__device__ __forceinline__ u64 pk2(float a, float b) {
  u64 r;
  asm("mov.b64 %0, {%1,%2};" : "=l"(r) : "f"(a), "f"(b));
  return r;
}
__device__ __forceinline__ void up2(u64 v, float& a, float& b) {
  asm("mov.b64 {%0,%1}, %2;" : "=f"(a), "=f"(b) : "l"(v));
}
__device__ __forceinline__ void fma2(u64& d_, u64 a, u64 b) {
  asm("fma.rn.f32x2 %0, %1, %2, %0;" : "+l"(d_) : "l"(a), "l"(b));
}
// 128-bit smem load -> two packed f32x2
__device__ __forceinline__ void ld128(const float* p, u64& a, u64& b) {
  float4 v = *reinterpret_cast<const float4*>(p);
  a = pk2(v.x, v.y);
  b = pk2(v.z, v.w);
}

// ---------------- precomputed tables (rotary + decay mask) ----------------
__device__ float g_sin[TT][16];
__device__ float g_cos[TT][16];
__device__ float g_dmask[HH][TT][TT];

__global__ void init_tables_kernel() {
  if (threadIdx.x != 0 || blockIdx.x != 0) return;
  double angle[16];
  for (int u = 0; u < 8; ++u) {
    double a = pow(10000.0, -(double)u / 7.0);
    angle[2 * u] = a;
    angle[2 * u + 1] = a;
  }
  for (int t = 0; t < TT; ++t)
    for (int d2 = 0; d2 < 16; ++d2) {
      g_sin[t][d2] = (float)sin((double)t * angle[d2]);
      g_cos[t][d2] = (float)cos((double)t * angle[d2]);
    }
  double l0 = log(1.0 / 32.0), l1 = log(1.0 / 512.0);
  for (int h = 0; h < HH; ++h) {
    double gamma = 1.0 - exp(l0 + (double)h * (l1 - l0) / 3.0);
    for (int n = 0; n < TT; ++n) {
      double vals[TT];
      double rs = 0.0;
      for (int m = 0; m < TT; ++m) {
        double v_ = 0.0;
        if (n >= m) v_ = pow(gamma, (double)(n - m));
        vals[m] = v_;
        rs += v_;
      }
      double inv = 1.0 / sqrt(rs);
      for (int m = 0; m < TT; ++m) g_dmask[h][n][m] = (float)(vals[m] * inv);
    }
  }
}

// ------- shared memory: every vector-read base is 16B-aligned -------
struct Smem {
  float h[TT][68];       // off 0     (1156 floats), rows 272B (16|)
  float xlT[DD][20];     // off 1156  rows 80B (16|)
  float q[TT][68];       // off 2436
  float k[TT][68];       // off 3592
  float gT[VDIM][20];    // off 4748
  float sT[HH][TT][20];  // off 7308
  float f[TT][FFND];     // off 8668, rows 48B (16|)
  float sin_[TT][16], cos_[TT][16];
  float mu[TT], rs[TT];
  float z[16];
};
union SmemU {
  Smem a;
  float img[3 * 32 * 32];
};

__global__ __launch_bounds__(128, 4) void vit_kernel(
    const float* __restrict__ x, const float* __restrict__ patch_w,
    const float* __restrict__ patch_b, const float* __restrict__ cls,
    const float* __restrict__ pos, const float* __restrict__ Wq,
    const float* __restrict__ Wk, const float* __restrict__ Wv,
    const float* __restrict__ Wg, const float* __restrict__ Wo,
    const float* __restrict__ ln1_s, const float* __restrict__ ln1_b,
    const float* __restrict__ w1, const float* __restrict__ b1,
    const float* __restrict__ w2, const float* __restrict__ b2,
    const float* __restrict__ ln2_s, const float* __restrict__ ln2_b,
    const float* __restrict__ lnf_s, const float* __restrict__ lnf_b,
    const float* __restrict__ neck_w, const float* __restrict__ neck_b,
    const float* __restrict__ head_w, const float* __restrict__ head_b,
    float* __restrict__ out) {
  extern __shared__ char smem_raw[];
  SmemU& U = *reinterpret_cast<SmemU*>(smem_raw);
  Smem& S = U.a;

  const int b = blockIdx.x;
  const int d = threadIdx.x;  // 0..127
  const int half = d >> 6;
  const int ch = d & 63;

  const float* xb = x + (size_t)b * 3072;
  for (int i = d; i < 3072; i += 128) U.img[i] = xb[i];
  __syncthreads();

  // ---------------- patch embedding (packed) ----------------
  float tokcol[8];
  const int pt0 = half ? 9 : 1;
  for (int i = 0; i < 8; ++i) {
    int t = pt0 + i;
    int p = t - 1, pr = p >> 2, pc = p & 3;
    float acc = patch_b[ch] + pos[t * DD + ch];
    u64 accp = 0;
    for (int c = 0; c < 3; ++c) {
#pragma unroll
      for (int i2 = 0; i2 < 8; ++i2) {
        const float* row = &U.img[c * 1024 + (pr * 8 + i2) * 32 + pc * 8];
        const float* wrow = &patch_w[(c * 64 + i2 * 8) * DD + ch];
        u64 r0, r1, r2, r3;
        ld128(row, r0, r1);
        ld128(row + 4, r2, r3);
        fma2(accp, r0, pk2(wrow[0], wrow[DD]));
        fma2(accp, r1, pk2(wrow[2 * DD], wrow[3 * DD]));
        fma2(accp, r2, pk2(wrow[4 * DD], wrow[5 * DD]));
        fma2(accp, r3, pk2(wrow[6 * DD], wrow[7 * DD]));
      }
    }
    float pa, pb;
    up2(accp, pa, pb);
    tokcol[i] = acc + pa + pb;
  }
  __syncthreads();  // img reads complete before S.* writes
#pragma unroll
  for (int i = 0; i < 8; ++i) S.h[pt0 + i][ch] = tokcol[i];
  if (half == 0) S.h[0][ch] = cls[ch] + pos[ch];
  for (int i = d; i < TT * 16; i += 128) {
    (&S.sin_[0][0])[i] = (&g_sin[0][0])[i];
    (&S.cos_[0][0])[i] = (&g_cos[0][0])[i];
  }
  __syncthreads();

  const float sgn = (ch & 1) ? 1.f : -1.f;
  const int dim = ch & 15;
  const int hh = d >> 5;
  const int tb = half ? 8 : 0;  // token split: 0-7 | 8-16
  const int tc = half ? 9 : 8;
  const u64 one2 = pk2(1.f, 1.f);

  // ---------------- transformer layers ----------------
  for (int L = 0; L < NLAYER; ++L) {
    // --- ln1 stats (single pass, vectorized) ---
    if (d < TT) {
      float s1 = 0.f, s2 = 0.f;
      for (int e = 0; e < DD; e += 4) {
        float4 v = *reinterpret_cast<const float4*>(&S.h[d][e]);
        s1 += (v.x + v.y) + (v.z + v.w);
        s2 += (v.x * v.x + v.y * v.y) + (v.z * v.z + v.w * v.w);
      }
      float mu = s1 * (1.f / DD);
      float var = s2 * (1.f / DD) - mu * mu;
      S.mu[d] = mu;
      S.rs[d] = rsqrtf(var + 1e-5f);
    }
    __syncthreads();
    {
      float sc = ln1_s[L * DD + ch], bi = ln1_b[L * DD + ch];
      for (int i = 0; i < tc; ++i) {
        int t = tb + i;
        S.xlT[ch][t] = (S.h[t][ch] - S.mu[t]) * S.rs[t] * sc + bi;
      }
    }
    __syncthreads();

    // --- fused QKVG projection (f32x2, vector loads) ---
    float vv[TT];
    {
      u64 a0p[8], avp[8], agp[8];
      float a0s = 0.f, avs = 0.f, ags = 0.f;
#pragma unroll
      for (int i = 0; i < 8; ++i) { a0p[i] = 0; avp[i] = 0; agp[i] = 0; }
      const float* W0 = half ? (Wk + L * DD * QKD) : (Wq + L * DD * QKD);
      const float* Wv_ = Wv + L * DD * VDIM;
      const float* Wg_ = Wg + L * DD * VDIM;
      for (int e = 0; e < DD; ++e) {
        float w0 = W0[e * QKD + ch];
        float wv = Wv_[e * VDIM + d];
        float wg = Wg_[e * VDIM + d];
        u64 w0p = pk2(w0, w0), wvp = pk2(wv, wv), wgp = pk2(wg, wg);
        const float* xr = &S.xlT[e][0];
        u64 xv[8];
        ld128(xr, xv[0], xv[1]);
        ld128(xr + 4, xv[2], xv[3]);
        ld128(xr + 8, xv[4], xv[5]);
        ld128(xr + 12, xv[6], xv[7]);
#pragma unroll
        for (int i = 0; i < 8; ++i) {
          fma2(a0p[i], xv[i], w0p);
          fma2(avp[i], xv[i], wvp);
          fma2(agp[i], xv[i], wgp);
        }
        float xs = xr[16];
        a0s += xs * w0;
        avs += xs * wv;
        ags += xs * wg;
      }
      float qa[TT], gg[TT];
#pragma unroll
      for (int i = 0; i < 8; ++i) {
        up2(a0p[i], qa[2 * i], qa[2 * i + 1]);
        up2(avp[i], vv[2 * i], vv[2 * i + 1]);
        up2(agp[i], gg[2 * i], gg[2 * i + 1]);
      }
      qa[16] = a0s;
      vv[16] = avs;
      gg[16] = ags;
#pragma unroll
      for (int t = 0; t < TT; ++t) {
        float an = __shfl_xor_sync(0xffffffffu, qa[t], 1);
        float cs = S.cos_[t][dim], sn = S.sin_[t][dim];
        float r = qa[t] * cs + sgn * an * sn;
        if (half == 0)
          S.q[t][ch] = r;
        else
          S.k[t][ch] = r * 0.25f;
        S.gT[d][t] = gg[t];
      }
    }
    __syncthreads();

    // --- scores = (q·k)*dmask -> sT[h][m][n] ---
    for (int idx = d; idx < HH * TT * TT; idx += 128) {
      int hs = idx / (TT * TT);
      int r = idx - hs * TT * TT;
      int n = r / TT, m = r - n * TT;
      const float* qr = &S.q[n][hs * 16];
      const float* kr = &S.k[m][hs * 16];
      u64 qv[8], kv[8];
      ld128(qr, qv[0], qv[1]);
      ld128(qr + 4, qv[2], qv[3]);
      ld128(qr + 8, qv[4], qv[5]);
      ld128(qr + 12, qv[6], qv[7]);
      ld128(kr, kv[0], kv[1]);
      ld128(kr + 4, kv[2], kv[3]);
      ld128(kr + 8, kv[4], kv[5]);
      ld128(kr + 12, kv[6], kv[7]);
      u64 acc = 0;
#pragma unroll
      for (int i = 0; i < 8; ++i) fma2(acc, qv[i], kv[i]);
      float lo, hi;
      up2(acc, lo, hi);
      S.sT[hs][m][n] = (lo + hi) * g_dmask[hs][n][m];
    }
    __syncthreads();

    // --- s@v + denom (packed); gnorm via warp shuffles; silu ---
    {
      u64 ocp[8], dsp[8];
      float ocs = 0.f, dss = 0.f;
#pragma unroll
      for (int i = 0; i < 8; ++i) { ocp[i] = 0; dsp[i] = 0; }
      const float* sbase = &S.sT[hh][0][0];
#pragma unroll
      for (int m = 0; m < TT; ++m) {
        float vm = vv[m];
        u64 vmp = pk2(vm, vm);
        const float* sr = sbase + m * 20;
        u64 sp[8];
        ld128(sr, sp[0], sp[1]);
        ld128(sr + 4, sp[2], sp[3]);
        ld128(sr + 8, sp[4], sp[5]);
        ld128(sr + 12, sp[6], sp[7]);
#pragma unroll
        for (int i = 0; i < 8; ++i) {
          fma2(ocp[i], sp[i], vmp);
          fma2(dsp[i], sp[i], one2);
        }
        float ss = sr[16];
        ocs += ss * vm;
        dss += ss;
      }
      float oc[TT], ds[TT];
#pragma unroll
      for (int i = 0; i < 8; ++i) {
        up2(ocp[i], oc[2 * i], oc[2 * i + 1]);
        up2(dsp[i], ds[2 * i], ds[2 * i + 1]);
      }
      oc[16] = ocs;
      ds[16] = dss;
#pragma unroll
      for (int n = 0; n < TT; ++n) {
        float o = oc[n] / fmaxf(fabsf(ds[n]), 1.f);
        float s1 = o, s2 = o * o;
#pragma unroll
        for (int off = 16; off; off >>= 1) {
          s1 += __shfl_xor_sync(0xffffffffu, s1, off);
          s2 += __shfl_xor_sync(0xffffffffu, s2, off);
        }
        float mu = s1 * (1.f / 32.f);
        float var = s2 * (1.f / 32.f) - mu * mu;
        float grs = rsqrtf(var + 1e-5f);
        float graw = S.gT[d][n];
        float sg = graw / (1.f + expf(-graw));
        S.gT[d][n] = sg * (o - mu) * grs;
      }
    }
    __syncthreads();

    // --- output projection + residual ---
    {
      const float* Wo_ = Wo + L * VDIM * DD;
      u64 rcp[4];
      float rcs = 0.f;
#pragma unroll
      for (int i = 0; i < 4; ++i) rcp[i] = 0;
      for (int c = 0; c < VDIM; ++c) {
        float w = Wo_[c * DD + ch];
        u64 wp = pk2(w, w);
        const float* gr = &S.gT[c][tb];  // tb=0 or 8: both 16B-aligned
        u64 g0, g1, g2, g3;
        ld128(gr, g0, g1);
        ld128(gr + 4, g2, g3);
        fma2(rcp[0], g0, wp);
        fma2(rcp[1], g1, wp);
        fma2(rcp[2], g2, wp);
        fma2(rcp[3], g3, wp);
        if (half) rcs += gr[8] * w;  // token 16
      }
#pragma unroll
      for (int i = 0; i < 4; ++i) {
        float a, bq;
        up2(rcp[i], a, bq);
        S.h[tb + 2 * i][ch] += a;
        S.h[tb + 2 * i + 1][ch] += bq;
      }
      if (half) S.h[16][ch] += rcs;
    }
    __syncthreads();

    // --- ln2 stats ---
    if (d < TT) {
      float s1 = 0.f, s2 = 0.f;
      for (int e = 0; e < DD; e += 4) {
        float4 v = *reinterpret_cast<const float4*>(&S.h[d][e]);
        s1 += (v.x + v.y) + (v.z + v.w);
        s2 += (v.x * v.x + v.y * v.y) + (v.z * v.z + v.w * v.w);
      }
      float mu = s1 * (1.f / DD);
      float var = s2 * (1.f / DD) - mu * mu;
      S.mu[d] = mu;
      S.rs[d] = rsqrtf(var + 1e-5f);
    }
    __syncthreads();
    {
      float sc = ln2_s[L * DD + ch], bi = ln2_b[L * DD + ch];
      for (int i = 0; i < tc; ++i) {
        int t = tb + i;
        S.xlT[ch][t] = (S.h[t][ch] - S.mu[t]) * S.rs[t] * sc + bi;
      }
    }
    __syncthreads();
    // --- FFN fc1 + gelu(tanh) ---
    for (int idx = d; idx < TT * FFND; idx += 128) {
      int n = idx / FFND, j = idx - n * FFND;
      float acc = b1[L * FFND + j];
      for (int e = 0; e < DD; ++e)
        acc += S.xlT[e][n] * w1[(L * DD + e) * FFND + j];
      float c3 = acc * acc * acc;
      S.f[n][j] = 0.5f * acc *
                  (1.f + tanhf(0.7978845608028654f * (acc + 0.044715f * c3)));
    }
    __syncthreads();
    // --- FFN fc2 + residual (packed over j pairs) ---
    {
      const float* W2 = w2 + L * FFND * DD + ch;
      float bb = b2[L * DD + ch];
      u64 wj[6];
#pragma unroll
      for (int jp = 0; jp < 6; ++jp)
        wj[jp] = pk2(W2[(2 * jp) * DD], W2[(2 * jp + 1) * DD]);
      for (int i = 0; i < tc; ++i) {
        int n = tb + i;
        const float* fr = &S.f[n][0];
        u64 f0, f1, f2, f3, f4, f5;
        ld128(fr, f0, f1);
        ld128(fr + 4, f2, f3);
        ld128(fr + 8, f4, f5);
        u64 acc = 0;
        fma2(acc, f0, wj[0]);
        fma2(acc, f1, wj[1]);
        fma2(acc, f2, wj[2]);
        fma2(acc, f3, wj[3]);
        fma2(acc, f4, wj[4]);
        fma2(acc, f5, wj[5]);
        float lo, hi;
        up2(acc, lo, hi);
        S.h[n][ch] += bb + lo + hi;
      }
    }
    __syncthreads();
  }

  // ---------------- final LN (token 16) + neck + head ----------------
  if (d == 0) {
    float s1 = 0.f, s2 = 0.f;
    for (int e = 0; e < DD; e += 4) {
      float4 v = *reinterpret_cast<const float4*>(&S.h[16][e]);
      s1 += (v.x + v.y) + (v.z + v.w);
      s2 += (v.x * v.x + v.y * v.y) + (v.z * v.z + v.w * v.w);
    }
    float mu = s1 * (1.f / DD);
    float var = s2 * (1.f / DD) - mu * mu;
    S.mu[0] = mu;
    S.rs[0] = rsqrtf(var + 1e-5f);
  }
  __syncthreads();
  if (d < 64)
    S.xlT[d][0] = (S.h[16][d] - S.mu[0]) * S.rs[0] * lnf_s[d] + lnf_b[d];
  __syncthreads();
  if (d < 16) {
    float acc = neck_b[d];
    for (int e = 0; e < DD; ++e) acc += S.xlT[e][0] * neck_w[e * 16 + d];
    S.z[d] = acc;
  }
  __syncthreads();
  if (d < 10) {
    float acc = head_b[d];
#pragma unroll
    for (int uu = 0; uu < 16; ++uu) acc += S.z[uu] * head_w[uu * 10 + d];
    out[(size_t)b * 10 + d] = acc;
  }
}

extern "C" void kernel_launch(void* const* d_in, const int* in_sizes, int n_in,
                              void* d_out, int out_size) {
  const float* x = (const float*)d_in[0];
  const float* patch_w = (const float*)d_in[1];
  const float* patch_b = (const float*)d_in[2];
  const float* cls = (const float*)d_in[3];
  const float* pos = (const float*)d_in[4];
  const float* Wq = (const float*)d_in[5];
  const float* Wk = (const float*)d_in[6];
  const float* Wv = (const float*)d_in[7];
  const float* Wg = (const float*)d_in[8];
  const float* Wo = (const float*)d_in[9];
  const float* ln1_s = (const float*)d_in[10];
  const float* ln1_b = (const float*)d_in[11];
  const float* w1 = (const float*)d_in[12];
  const float* b1 = (const float*)d_in[13];
  const float* w2 = (const float*)d_in[14];
  const float* b2 = (const float*)d_in[15];
  const float* ln2_s = (const float*)d_in[16];
  const float* ln2_b = (const float*)d_in[17];
  const float* lnf_s = (const float*)d_in[18];
  const float* lnf_b = (const float*)d_in[19];
  const float* neck_w = (const float*)d_in[20];
  const float* neck_b = (const float*)d_in[21];
  const float* head_w = (const float*)d_in[22];
  const float* head_b = (const float*)d_in[23];
  float* out = (float*)d_out;

  int B = in_sizes[0] / 3072;
  size_t smem_bytes = sizeof(SmemU);
  (void)cudaFuncSetAttribute(
      vit_kernel, cudaFuncAttributeMaxDynamicSharedMemorySize, (int)smem_bytes);

  init_tables_kernel<<<1, 1>>>();
  vit_kernel<<<B, 128, smem_bytes>>>(x, patch_w, patch_b, cls, pos, Wq, Wk, Wv,
                                     Wg, Wo, ln1_s, ln1_b, w1, b1, w2, b2,
                                     ln2_s, ln2_b, lnf_s, lnf_b, neck_w, neck_b,
                                     head_w, head_b, out);
}

// round 11
// speedup vs baseline: 1.6925x; 1.0172x over previous
#include <cuda_runtime.h>
#include <math.h>

#define NLAYER 8
#define HH 4
#define DD 64
#define QKD 64
#define VDIM 128
#define TT 17
#define FFND 12

typedef unsigned long long u64;

// ---------------- f32x2 helpers ----------------
__device__ __forceinline__ u64 pk2(float a, float b) {
  u64 r;
  asm("mov.b64 %0, {%1,%2};" : "=l"(r) : "f"(a), "f"(b));
  return r;
}
__device__ __forceinline__ void up2(u64 v, float& a, float& b) {
  asm("mov.b64 {%0,%1}, %2;" : "=f"(a), "=f"(b) : "l"(v));
}
__device__ __forceinline__ void fma2(u64& d_, u64 a, u64 b) {
  asm("fma.rn.f32x2 %0, %1, %2, %0;" : "+l"(d_) : "l"(a), "l"(b));
}
__device__ __forceinline__ void ld128(const float* p, u64& a, u64& b) {
  float4 v = *reinterpret_cast<const float4*>(p);
  a = pk2(v.x, v.y);
  b = pk2(v.z, v.w);
}
__device__ __forceinline__ u64 ld64(const float* p) {
  return *reinterpret_cast<const u64*>(p);
}
__device__ __forceinline__ void st64(float* p, u64 v) {
  *reinterpret_cast<u64*>(p) = v;
}

// ---------------- precomputed tables ----------------
__device__ float g_sin[TT][16];
__device__ float g_cos[TT][16];
__device__ float g_dmask[HH][TT][20];  // padded rows (16B-aligned)

__global__ void init_tables_kernel() {
  if (threadIdx.x != 0 || blockIdx.x != 0) return;
  double angle[16];
  for (int u = 0; u < 8; ++u) {
    double a = pow(10000.0, -(double)u / 7.0);
    angle[2 * u] = a;
    angle[2 * u + 1] = a;
  }
  for (int t = 0; t < TT; ++t)
    for (int d2 = 0; d2 < 16; ++d2) {
      g_sin[t][d2] = (float)sin((double)t * angle[d2]);
      g_cos[t][d2] = (float)cos((double)t * angle[d2]);
    }
  double l0 = log(1.0 / 32.0), l1 = log(1.0 / 512.0);
  for (int h = 0; h < HH; ++h) {
    double gamma = 1.0 - exp(l0 + (double)h * (l1 - l0) / 3.0);
    for (int n = 0; n < TT; ++n) {
      double vals[TT];
      double rs = 0.0;
      for (int m = 0; m < TT; ++m) {
        double v_ = 0.0;
        if (n >= m) v_ = pow(gamma, (double)(n - m));
        vals[m] = v_;
        rs += v_;
      }
      double inv = 1.0 / sqrt(rs);
      for (int m = 0; m < TT; ++m) g_dmask[h][n][m] = (float)(vals[m] * inv);
      for (int m = TT; m < 20; ++m) g_dmask[h][n][m] = 0.f;
    }
  }
}

// ---------------- shared memory (vector bases 16B-aligned) ----------------
struct Smem {
  float h[TT][68];       // residual [t][ch]
  float xlT[DD][20];     // LN out [ch][t], t=17 pad 0
  float qT[DD][20];      // post-rotary q [ch][t]
  float kT[DD][20];      // post-rotary scaled k [ch][t]
  float gT[VDIM][20];    // [c][t]: raw g, then post-silu
  float sT[HH][TT][20];  // scores [h][m][n], n=17 col zeroed
  float f[TT][FFND];
  float sin_[TT][16], cos_[TT][16];
  float mu[TT], rs[TT];
  float z[16];
};
union SmemU {
  Smem a;
  float img[3 * 32 * 32];
};

__global__ __launch_bounds__(128, 4) void vit_kernel(
    const float* __restrict__ x, const float* __restrict__ patch_w,
    const float* __restrict__ patch_b, const float* __restrict__ cls,
    const float* __restrict__ pos, const float* __restrict__ Wq,
    const float* __restrict__ Wk, const float* __restrict__ Wv,
    const float* __restrict__ Wg, const float* __restrict__ Wo,
    const float* __restrict__ ln1_s, const float* __restrict__ ln1_b,
    const float* __restrict__ w1, const float* __restrict__ b1,
    const float* __restrict__ w2, const float* __restrict__ b2,
    const float* __restrict__ ln2_s, const float* __restrict__ ln2_b,
    const float* __restrict__ lnf_s, const float* __restrict__ lnf_b,
    const float* __restrict__ neck_w, const float* __restrict__ neck_b,
    const float* __restrict__ head_w, const float* __restrict__ head_b,
    float* __restrict__ out) {
  extern __shared__ char smem_raw[];
  SmemU& U = *reinterpret_cast<SmemU*>(smem_raw);
  Smem& S = U.a;

  const int b = blockIdx.x;
  const int d = threadIdx.x;  // 0..127
  const int half = d >> 6;
  const int ch = d & 63;

  const float* xb = x + (size_t)b * 3072;
  for (int i = d; i < 3072; i += 128) U.img[i] = xb[i];
  __syncthreads();

  // ---------------- patch embedding ----------------
  float tokcol[8];
  const int pt0 = half ? 9 : 1;
  for (int i = 0; i < 8; ++i) {
    int t = pt0 + i;
    int p = t - 1, pr = p >> 2, pc = p & 3;
    float acc = patch_b[ch] + pos[t * DD + ch];
    u64 accp = 0;
    for (int c = 0; c < 3; ++c) {
#pragma unroll
      for (int i2 = 0; i2 < 8; ++i2) {
        const float* row = &U.img[c * 1024 + (pr * 8 + i2) * 32 + pc * 8];
        const float* wrow = &patch_w[(c * 64 + i2 * 8) * DD + ch];
        u64 r0, r1, r2, r3;
        ld128(row, r0, r1);
        ld128(row + 4, r2, r3);
        fma2(accp, r0, pk2(wrow[0], wrow[DD]));
        fma2(accp, r1, pk2(wrow[2 * DD], wrow[3 * DD]));
        fma2(accp, r2, pk2(wrow[4 * DD], wrow[5 * DD]));
        fma2(accp, r3, pk2(wrow[6 * DD], wrow[7 * DD]));
      }
    }
    float pa, pb;
    up2(accp, pa, pb);
    tokcol[i] = acc + pa + pb;
  }
  __syncthreads();  // img reads complete
#pragma unroll
  for (int i = 0; i < 8; ++i) S.h[pt0 + i][ch] = tokcol[i];
  if (half == 0) S.h[0][ch] = cls[ch] + pos[ch];
  for (int i = d; i < TT * 16; i += 128) {
    (&S.sin_[0][0])[i] = (&g_sin[0][0])[i];
    (&S.cos_[0][0])[i] = (&g_cos[0][0])[i];
  }
  // zero the n=17 column of sT once (never rewritten)
  if (d < HH * TT) S.sT[d / TT][d % TT][17] = 0.f;
  __syncthreads();

  const float sgn = (ch & 1) ? 1.f : -1.f;
  const int dim = ch & 15;
  const int hh = d >> 5;
  const int tb = half ? 8 : 0;
  const int tc = half ? 9 : 8;
  const u64 one2 = pk2(1.f, 1.f);

  for (int L = 0; L < NLAYER; ++L) {
    // --- ln1 stats ---
    if (d < TT) {
      float s1 = 0.f, s2 = 0.f;
      for (int e = 0; e < DD; e += 4) {
        float4 v = *reinterpret_cast<const float4*>(&S.h[d][e]);
        s1 += (v.x + v.y) + (v.z + v.w);
        s2 += (v.x * v.x + v.y * v.y) + (v.z * v.z + v.w * v.w);
      }
      float mu = s1 * (1.f / DD);
      S.mu[d] = mu;
      S.rs[d] = rsqrtf(s2 * (1.f / DD) - mu * mu + 1e-5f);
    }
    __syncthreads();
    {
      float sc = ln1_s[L * DD + ch], bi = ln1_b[L * DD + ch];
      for (int i = 0; i < tc; ++i) {
        int t = tb + i;
        S.xlT[ch][t] = (S.h[t][ch] - S.mu[t]) * S.rs[t] * sc + bi;
      }
      if (half) S.xlT[ch][17] = 0.f;  // token pad
    }
    __syncthreads();

    // --- fused QKVG projection (18-token pairs) ---
    float vv[18];
    {
      u64 a0p[9], avp[9], agp[9];
#pragma unroll
      for (int i = 0; i < 9; ++i) { a0p[i] = 0; avp[i] = 0; agp[i] = 0; }
      const float* W0 = half ? (Wk + L * DD * QKD) : (Wq + L * DD * QKD);
      const float* Wv_ = Wv + L * DD * VDIM;
      const float* Wg_ = Wg + L * DD * VDIM;
      for (int e = 0; e < DD; ++e) {
        float w0 = W0[e * QKD + ch];
        float wv = Wv_[e * VDIM + d];
        float wg = Wg_[e * VDIM + d];
        u64 w0p = pk2(w0, w0), wvp = pk2(wv, wv), wgp = pk2(wg, wg);
        const float* xr = &S.xlT[e][0];
        u64 xv[9];
        ld128(xr, xv[0], xv[1]);
        ld128(xr + 4, xv[2], xv[3]);
        ld128(xr + 8, xv[4], xv[5]);
        ld128(xr + 12, xv[6], xv[7]);
        xv[8] = ld64(xr + 16);
#pragma unroll
        for (int i = 0; i < 9; ++i) {
          fma2(a0p[i], xv[i], w0p);
          fma2(avp[i], xv[i], wvp);
          fma2(agp[i], xv[i], wgp);
        }
      }
      float qa[18], gg[18];
#pragma unroll
      for (int i = 0; i < 9; ++i) {
        up2(a0p[i], qa[2 * i], qa[2 * i + 1]);
        up2(avp[i], vv[2 * i], vv[2 * i + 1]);
        up2(agp[i], gg[2 * i], gg[2 * i + 1]);
      }
      // rotary on qa (t<17); write qT|kT and raw gT as 64-bit pairs
      float r[18];
#pragma unroll
      for (int t = 0; t < TT; ++t) {
        float an = __shfl_xor_sync(0xffffffffu, qa[t], 1);
        float cs = S.cos_[t][dim], sn = S.sin_[t][dim];
        r[t] = qa[t] * cs + sgn * an * sn;
        if (half) r[t] *= 0.25f;
      }
      r[17] = 0.f;
      float* dst = half ? &S.kT[ch][0] : &S.qT[ch][0];
#pragma unroll
      for (int i = 0; i < 9; ++i) {
        st64(dst + 2 * i, pk2(r[2 * i], r[2 * i + 1]));
        st64(&S.gT[d][2 * i], pk2(gg[2 * i], gg[2 * i + 1]));
      }
    }
    __syncthreads();

    // --- scores: items (hs, n, m-group of 4), conflict-free reads ---
    for (int idx = d; idx < HH * TT * 5; idx += 128) {
      int mg = idx % 5;
      int rest = idx / 5;
      int n = rest % TT;
      int hs = rest / TT;
      u64 acc0 = 0, acc1 = 0;
      const float* qcol = &S.qT[hs * 16][n];
      const float* krow = &S.kT[hs * 16][4 * mg];
#pragma unroll
      for (int e = 0; e < 16; ++e) {
        float qs = qcol[e * 20];
        u64 k0, k1;
        ld128(krow + e * 20, k0, k1);
        u64 qp = pk2(qs, qs);
        fma2(acc0, qp, k0);
        fma2(acc1, qp, k1);
      }
      float s0, s1, s2, s3;
      up2(acc0, s0, s1);
      up2(acc1, s2, s3);
      const float* dm = &g_dmask[hs][n][4 * mg];
      int m0 = 4 * mg;
      S.sT[hs][m0][n] = s0 * dm[0];
      if (m0 + 1 < TT) S.sT[hs][m0 + 1][n] = s1 * dm[1];
      if (m0 + 2 < TT) S.sT[hs][m0 + 2][n] = s2 * dm[2];
      if (m0 + 3 < TT) S.sT[hs][m0 + 3][n] = s3 * dm[3];
    }
    __syncthreads();

    // --- s@v + denom; gnorm via warp shuffles; silu; write gT pairs ---
    {
      u64 ocp[9], dsp[9];
#pragma unroll
      for (int i = 0; i < 9; ++i) { ocp[i] = 0; dsp[i] = 0; }
      const float* sbase = &S.sT[hh][0][0];
#pragma unroll
      for (int m = 0; m < TT; ++m) {
        float vm = vv[m];
        u64 vmp = pk2(vm, vm);
        const float* sr = sbase + m * 20;
        u64 sp[9];
        ld128(sr, sp[0], sp[1]);
        ld128(sr + 4, sp[2], sp[3]);
        ld128(sr + 8, sp[4], sp[5]);
        ld128(sr + 12, sp[6], sp[7]);
        sp[8] = ld64(sr + 16);
#pragma unroll
        for (int i = 0; i < 9; ++i) {
          fma2(ocp[i], sp[i], vmp);
          fma2(dsp[i], sp[i], one2);
        }
      }
      float oc[18], ds[18];
#pragma unroll
      for (int i = 0; i < 9; ++i) {
        up2(ocp[i], oc[2 * i], oc[2 * i + 1]);
        up2(dsp[i], ds[2 * i], ds[2 * i + 1]);
      }
      // load raw g pairs (own row)
      float gg[18];
#pragma unroll
      for (int i = 0; i < 9; ++i)
        up2(ld64(&S.gT[d][2 * i]), gg[2 * i], gg[2 * i + 1]);
      float res[18];
#pragma unroll
      for (int n = 0; n < TT; ++n) {
        float o = oc[n] / fmaxf(fabsf(ds[n]), 1.f);
        float s1 = o, s2 = o * o;
#pragma unroll
        for (int off = 16; off; off >>= 1) {
          s1 += __shfl_xor_sync(0xffffffffu, s1, off);
          s2 += __shfl_xor_sync(0xffffffffu, s2, off);
        }
        float mu = s1 * (1.f / 32.f);
        float grs = rsqrtf(s2 * (1.f / 32.f) - mu * mu + 1e-5f);
        float sg = gg[n] / (1.f + expf(-gg[n]));
        res[n] = sg * (o - mu) * grs;
      }
      res[17] = 0.f;
      __syncthreads();
#pragma unroll
      for (int i = 0; i < 9; ++i)
        st64(&S.gT[d][2 * i], pk2(res[2 * i], res[2 * i + 1]));
    }
    __syncthreads();

    // --- output projection + residual ---
    {
      const float* Wo_ = Wo + L * VDIM * DD;
      u64 rcp[5];
#pragma unroll
      for (int i = 0; i < 5; ++i) rcp[i] = 0;
      for (int c = 0; c < VDIM; ++c) {
        float w = Wo_[c * DD + ch];
        u64 wp = pk2(w, w);
        const float* gr = &S.gT[c][tb];
        u64 g0, g1;
        ld128(gr, g0, g1);
        fma2(rcp[0], g0, wp);
        fma2(rcp[1], g1, wp);
        ld128(gr + 4, g0, g1);
        fma2(rcp[2], g0, wp);
        fma2(rcp[3], g1, wp);
        if (half) fma2(rcp[4], ld64(gr + 8), wp);  // tokens 16,17(=0)
      }
#pragma unroll
      for (int i = 0; i < 4; ++i) {
        float a, bq;
        up2(rcp[i], a, bq);
        S.h[tb + 2 * i][ch] += a;
        S.h[tb + 2 * i + 1][ch] += bq;
      }
      if (half) {
        float a, bq;
        up2(rcp[4], a, bq);
        S.h[16][ch] += a;
      }
    }
    __syncthreads();

    // --- ln2 ---
    if (d < TT) {
      float s1 = 0.f, s2 = 0.f;
      for (int e = 0; e < DD; e += 4) {
        float4 v = *reinterpret_cast<const float4*>(&S.h[d][e]);
        s1 += (v.x + v.y) + (v.z + v.w);
        s2 += (v.x * v.x + v.y * v.y) + (v.z * v.z + v.w * v.w);
      }
      float mu = s1 * (1.f / DD);
      S.mu[d] = mu;
      S.rs[d] = rsqrtf(s2 * (1.f / DD) - mu * mu + 1e-5f);
    }
    __syncthreads();
    {
      float sc = ln2_s[L * DD + ch], bi = ln2_b[L * DD + ch];
      for (int i = 0; i < tc; ++i) {
        int t = tb + i;
        S.xlT[ch][t] = (S.h[t][ch] - S.mu[t]) * S.rs[t] * sc + bi;
      }
      if (half) S.xlT[ch][17] = 0.f;
    }
    __syncthreads();
    // --- FFN fc1 + gelu(tanh) ---
    for (int idx = d; idx < TT * FFND; idx += 128) {
      int n = idx / FFND, j = idx - n * FFND;
      float acc = b1[L * FFND + j];
      for (int e = 0; e < DD; ++e)
        acc += S.xlT[e][n] * w1[(L * DD + e) * FFND + j];
      float c3 = acc * acc * acc;
      S.f[n][j] = 0.5f * acc *
                  (1.f + tanhf(0.7978845608028654f * (acc + 0.044715f * c3)));
    }
    __syncthreads();
    // --- FFN fc2 + residual ---
    {
      const float* W2 = w2 + L * FFND * DD + ch;
      float bb = b2[L * DD + ch];
      u64 wj[6];
#pragma unroll
      for (int jp = 0; jp < 6; ++jp)
        wj[jp] = pk2(W2[(2 * jp) * DD], W2[(2 * jp + 1) * DD]);
      for (int i = 0; i < tc; ++i) {
        int n = tb + i;
        const float* fr = &S.f[n][0];
        u64 f0, f1, f2, f3, f4, f5;
        ld128(fr, f0, f1);
        ld128(fr + 4, f2, f3);
        ld128(fr + 8, f4, f5);
        u64 acc = 0;
        fma2(acc, f0, wj[0]);
        fma2(acc, f1, wj[1]);
        fma2(acc, f2, wj[2]);
        fma2(acc, f3, wj[3]);
        fma2(acc, f4, wj[4]);
        fma2(acc, f5, wj[5]);
        float lo, hi;
        up2(acc, lo, hi);
        S.h[n][ch] += bb + lo + hi;
      }
    }
    __syncthreads();
  }

  // ---------------- final LN (token 16) + neck + head ----------------
  if (d == 0) {
    float s1 = 0.f, s2 = 0.f;
    for (int e = 0; e < DD; e += 4) {
      float4 v = *reinterpret_cast<const float4*>(&S.h[16][e]);
      s1 += (v.x + v.y) + (v.z + v.w);
      s2 += (v.x * v.x + v.y * v.y) + (v.z * v.z + v.w * v.w);
    }
    float mu = s1 * (1.f / DD);
    S.mu[0] = mu;
    S.rs[0] = rsqrtf(s2 * (1.f / DD) - mu * mu + 1e-5f);
  }
  __syncthreads();
  if (d < 64)
    S.xlT[d][0] = (S.h[16][d] - S.mu[0]) * S.rs[0] * lnf_s[d] + lnf_b[d];
  __syncthreads();
  if (d < 16) {
    float acc = neck_b[d];
    for (int e = 0; e < DD; ++e) acc += S.xlT[e][0] * neck_w[e * 16 + d];
    S.z[d] = acc;
  }
  __syncthreads();
  if (d < 10) {
    float acc = head_b[d];
#pragma unroll
    for (int uu = 0; uu < 16; ++uu) acc += S.z[uu] * head_w[uu * 10 + d];
    out[(size_t)b * 10 + d] = acc;
  }
}

extern "C" void kernel_launch(void* const* d_in, const int* in_sizes, int n_in,
                              void* d_out, int out_size) {
  const float* x = (const float*)d_in[0];
  const float* patch_w = (const float*)d_in[1];
  const float* patch_b = (const float*)d_in[2];
  const float* cls = (const float*)d_in[3];
  const float* pos = (const float*)d_in[4];
  const float* Wq = (const float*)d_in[5];
  const float* Wk = (const float*)d_in[6];
  const float* Wv = (const float*)d_in[7];
  const float* Wg = (const float*)d_in[8];
  const float* Wo = (const float*)d_in[9];
  const float* ln1_s = (const float*)d_in[10];
  const float* ln1_b = (const float*)d_in[11];
  const float* w1 = (const float*)d_in[12];
  const float* b1 = (const float*)d_in[13];
  const float* w2 = (const float*)d_in[14];
  const float* b2 = (const float*)d_in[15];
  const float* ln2_s = (const float*)d_in[16];
  const float* ln2_b = (const float*)d_in[17];
  const float* lnf_s = (const float*)d_in[18];
  const float* lnf_b = (const float*)d_in[19];
  const float* neck_w = (const float*)d_in[20];
  const float* neck_b = (const float*)d_in[21];
  const float* head_w = (const float*)d_in[22];
  const float* head_b = (const float*)d_in[23];
  float* out = (float*)d_out;

  int B = in_sizes[0] / 3072;
  size_t smem_bytes = sizeof(SmemU);
  (void)cudaFuncSetAttribute(
      vit_kernel, cudaFuncAttributeMaxDynamicSharedMemorySize, (int)smem_bytes);

  init_tables_kernel<<<1, 1>>>();
  vit_kernel<<<B, 128, smem_bytes>>>(x, patch_w, patch_b, cls, pos, Wq, Wk, Wv,
                                     Wg, Wo, ln1_s, ln1_b, w1, b1, w2, b2,
                                     ln2_s, ln2_b, lnf_s, lnf_b, neck_w, neck_b,
                                     head_w, head_b, out);
}

// round 12
// speedup vs baseline: 1.7026x; 1.0060x over previous
#include <cuda_runtime.h>
#include <math.h>

#define NLAYER 8
#define HH 4
#define DD 64
#define QKD 64
#define VDIM 128
#define TT 17
#define FFND 12

typedef unsigned long long u64;

// ---------------- f32x2 helpers ----------------
__device__ __forceinline__ u64 pk2(float a, float b) {
  u64 r;
  asm("mov.b64 %0, {%1,%2};" : "=l"(r) : "f"(a), "f"(b));
  return r;
}
__device__ __forceinline__ void up2(u64 v, float& a, float& b) {
  asm("mov.b64 {%0,%1}, %2;" : "=f"(a), "=f"(b) : "l"(v));
}
__device__ __forceinline__ void fma2(u64& d_, u64 a, u64 b) {
  asm("fma.rn.f32x2 %0, %1, %2, %0;" : "+l"(d_) : "l"(a), "l"(b));
}
__device__ __forceinline__ void ld128(const float* p, u64& a, u64& b) {
  float4 v = *reinterpret_cast<const float4*>(p);
  a = pk2(v.x, v.y);
  b = pk2(v.z, v.w);
}
__device__ __forceinline__ u64 ld64(const float* p) {
  return *reinterpret_cast<const u64*>(p);
}
__device__ __forceinline__ void st64(float* p, u64 v) {
  *reinterpret_cast<u64*>(p) = v;
}

// ---------------- precomputed tables ----------------
__device__ float g_sin[TT][16];
__device__ float g_cos[TT][16];
__device__ float g_dmask[HH][TT][20];  // padded rows (16B-aligned)

__global__ void init_tables_kernel() {
  if (threadIdx.x != 0 || blockIdx.x != 0) return;
  double angle[16];
  for (int u = 0; u < 8; ++u) {
    double a = pow(10000.0, -(double)u / 7.0);
    angle[2 * u] = a;
    angle[2 * u + 1] = a;
  }
  for (int t = 0; t < TT; ++t)
    for (int d2 = 0; d2 < 16; ++d2) {
      g_sin[t][d2] = (float)sin((double)t * angle[d2]);
      g_cos[t][d2] = (float)cos((double)t * angle[d2]);
    }
  double l0 = log(1.0 / 32.0), l1 = log(1.0 / 512.0);
  for (int h = 0; h < HH; ++h) {
    double gamma = 1.0 - exp(l0 + (double)h * (l1 - l0) / 3.0);
    for (int n = 0; n < TT; ++n) {
      double vals[TT];
      double rs = 0.0;
      for (int m = 0; m < TT; ++m) {
        double v_ = 0.0;
        if (n >= m) v_ = pow(gamma, (double)(n - m));
        vals[m] = v_;
        rs += v_;
      }
      double inv = 1.0 / sqrt(rs);
      for (int m = 0; m < TT; ++m) g_dmask[h][n][m] = (float)(vals[m] * inv);
      for (int m = TT; m < 20; ++m) g_dmask[h][n][m] = 0.f;
    }
  }
}

// ---------------- shared memory (vector bases 16B-aligned) ----------------
struct Smem {
  float h[TT][68];       // residual [t][ch]
  float xlT[DD][20];     // LN out [ch][t], t=17 pad 0
  float qT[DD][20];      // post-rotary q [ch][t]
  float kT[DD][20];      // post-rotary scaled k [ch][t]
  float gT[VDIM][20];    // [c][t]: raw g, then post-silu
  float sT[HH][TT][20];  // scores [h][m][n], n=17 col zeroed
  float f[TT][FFND];
  float sin_[TT][16], cos_[TT][16];
  float mu[TT], rs[TT];
  float z[16];
};
union SmemU {
  Smem a;
  float img[3 * 32 * 32];
};

// warp-parallel LN stats: warp w covers tokens 4w..4w+3 (+ token 16 on warp 0)
__device__ __forceinline__ void ln_stats(Smem& S, int d) {
  int wrp = d >> 5, lane = d & 31;
  int cnt = (wrp == 0) ? 5 : 4;
  for (int i = 0; i < cnt; ++i) {
    int t = (i == 4) ? 16 : (wrp * 4 + i);
    float a, b;
    up2(ld64(&S.h[t][2 * lane]), a, b);
    float s1 = a + b, s2 = a * a + b * b;
#pragma unroll
    for (int off = 16; off; off >>= 1) {
      s1 += __shfl_xor_sync(0xffffffffu, s1, off);
      s2 += __shfl_xor_sync(0xffffffffu, s2, off);
    }
    if (lane == 0) {
      float mu = s1 * (1.f / DD);
      S.mu[t] = mu;
      S.rs[t] = rsqrtf(s2 * (1.f / DD) - mu * mu + 1e-5f);
    }
  }
}

__global__ __launch_bounds__(128, 5) void vit_kernel(
    const float* __restrict__ x, const float* __restrict__ patch_w,
    const float* __restrict__ patch_b, const float* __restrict__ cls,
    const float* __restrict__ pos, const float* __restrict__ Wq,
    const float* __restrict__ Wk, const float* __restrict__ Wv,
    const float* __restrict__ Wg, const float* __restrict__ Wo,
    const float* __restrict__ ln1_s, const float* __restrict__ ln1_b,
    const float* __restrict__ w1, const float* __restrict__ b1,
    const float* __restrict__ w2, const float* __restrict__ b2,
    const float* __restrict__ ln2_s, const float* __restrict__ ln2_b,
    const float* __restrict__ lnf_s, const float* __restrict__ lnf_b,
    const float* __restrict__ neck_w, const float* __restrict__ neck_b,
    const float* __restrict__ head_w, const float* __restrict__ head_b,
    float* __restrict__ out) {
  extern __shared__ char smem_raw[];
  SmemU& U = *reinterpret_cast<SmemU*>(smem_raw);
  Smem& S = U.a;

  const int b = blockIdx.x;
  const int d = threadIdx.x;  // 0..127
  const int half = d >> 6;
  const int ch = d & 63;

  const float* xb = x + (size_t)b * 3072;
  for (int i = d; i < 3072; i += 128) U.img[i] = xb[i];
  __syncthreads();

  // ---------------- patch embedding ----------------
  float tokcol[8];
  const int pt0 = half ? 9 : 1;
  for (int i = 0; i < 8; ++i) {
    int t = pt0 + i;
    int p = t - 1, pr = p >> 2, pc = p & 3;
    float acc = patch_b[ch] + pos[t * DD + ch];
    u64 accp = 0;
    for (int c = 0; c < 3; ++c) {
#pragma unroll
      for (int i2 = 0; i2 < 8; ++i2) {
        const float* row = &U.img[c * 1024 + (pr * 8 + i2) * 32 + pc * 8];
        const float* wrow = &patch_w[(c * 64 + i2 * 8) * DD + ch];
        u64 r0, r1, r2, r3;
        ld128(row, r0, r1);
        ld128(row + 4, r2, r3);
        fma2(accp, r0, pk2(wrow[0], wrow[DD]));
        fma2(accp, r1, pk2(wrow[2 * DD], wrow[3 * DD]));
        fma2(accp, r2, pk2(wrow[4 * DD], wrow[5 * DD]));
        fma2(accp, r3, pk2(wrow[6 * DD], wrow[7 * DD]));
      }
    }
    float pa, pb;
    up2(accp, pa, pb);
    tokcol[i] = acc + pa + pb;
  }
  __syncthreads();  // img reads complete
#pragma unroll
  for (int i = 0; i < 8; ++i) S.h[pt0 + i][ch] = tokcol[i];
  if (half == 0) S.h[0][ch] = cls[ch] + pos[ch];
  for (int i = d; i < TT * 16; i += 128) {
    (&S.sin_[0][0])[i] = (&g_sin[0][0])[i];
    (&S.cos_[0][0])[i] = (&g_cos[0][0])[i];
  }
  // zero the n=17 column of sT once (never rewritten)
  if (d < HH * TT) S.sT[d / TT][d % TT][17] = 0.f;
  __syncthreads();

  const float sgn = (ch & 1) ? 1.f : -1.f;
  const int dim = ch & 15;
  const int hh = d >> 5;
  const int tb = half ? 8 : 0;
  const int tc = half ? 9 : 8;
  const u64 one2 = pk2(1.f, 1.f);

  for (int L = 0; L < NLAYER; ++L) {
    // --- ln1 stats (warp-parallel) ---
    ln_stats(S, d);
    __syncthreads();
    {
      float sc = ln1_s[L * DD + ch], bi = ln1_b[L * DD + ch];
      for (int i = 0; i < tc; ++i) {
        int t = tb + i;
        S.xlT[ch][t] = (S.h[t][ch] - S.mu[t]) * S.rs[t] * sc + bi;
      }
      if (half) S.xlT[ch][17] = 0.f;  // token pad
    }
    __syncthreads();

    // --- fused QKVG projection (18-token pairs) ---
    float vv[18];
    {
      u64 a0p[9], avp[9], agp[9];
#pragma unroll
      for (int i = 0; i < 9; ++i) { a0p[i] = 0; avp[i] = 0; agp[i] = 0; }
      const float* W0 = half ? (Wk + L * DD * QKD) : (Wq + L * DD * QKD);
      const float* Wv_ = Wv + L * DD * VDIM;
      const float* Wg_ = Wg + L * DD * VDIM;
      for (int e = 0; e < DD; ++e) {
        float w0 = W0[e * QKD + ch];
        float wv = Wv_[e * VDIM + d];
        float wg = Wg_[e * VDIM + d];
        u64 w0p = pk2(w0, w0), wvp = pk2(wv, wv), wgp = pk2(wg, wg);
        const float* xr = &S.xlT[e][0];
        u64 xv[9];
        ld128(xr, xv[0], xv[1]);
        ld128(xr + 4, xv[2], xv[3]);
        ld128(xr + 8, xv[4], xv[5]);
        ld128(xr + 12, xv[6], xv[7]);
        xv[8] = ld64(xr + 16);
#pragma unroll
        for (int i = 0; i < 9; ++i) {
          fma2(a0p[i], xv[i], w0p);
          fma2(avp[i], xv[i], wvp);
          fma2(agp[i], xv[i], wgp);
        }
      }
      float qa[18], gg[18];
#pragma unroll
      for (int i = 0; i < 9; ++i) {
        up2(a0p[i], qa[2 * i], qa[2 * i + 1]);
        up2(avp[i], vv[2 * i], vv[2 * i + 1]);
        up2(agp[i], gg[2 * i], gg[2 * i + 1]);
      }
      // rotary on qa (t<17); write qT|kT and raw gT as 64-bit pairs
      float r[18];
#pragma unroll
      for (int t = 0; t < TT; ++t) {
        float an = __shfl_xor_sync(0xffffffffu, qa[t], 1);
        float cs = S.cos_[t][dim], sn = S.sin_[t][dim];
        r[t] = qa[t] * cs + sgn * an * sn;
        if (half) r[t] *= 0.25f;
      }
      r[17] = 0.f;
      float* dst = half ? &S.kT[ch][0] : &S.qT[ch][0];
#pragma unroll
      for (int i = 0; i < 9; ++i) {
        st64(dst + 2 * i, pk2(r[2 * i], r[2 * i + 1]));
        st64(&S.gT[d][2 * i], pk2(gg[2 * i], gg[2 * i + 1]));
      }
    }
    __syncthreads();

    // --- scores: items (hs, n, m-group of 4), conflict-free reads ---
    for (int idx = d; idx < HH * TT * 5; idx += 128) {
      int mg = idx % 5;
      int rest = idx / 5;
      int n = rest % TT;
      int hs = rest / TT;
      u64 acc0 = 0, acc1 = 0;
      const float* qcol = &S.qT[hs * 16][n];
      const float* krow = &S.kT[hs * 16][4 * mg];
#pragma unroll
      for (int e = 0; e < 16; ++e) {
        float qs = qcol[e * 20];
        u64 k0, k1;
        ld128(krow + e * 20, k0, k1);
        u64 qp = pk2(qs, qs);
        fma2(acc0, qp, k0);
        fma2(acc1, qp, k1);
      }
      float s0, s1, s2, s3;
      up2(acc0, s0, s1);
      up2(acc1, s2, s3);
      const float* dm = &g_dmask[hs][n][4 * mg];
      int m0 = 4 * mg;
      S.sT[hs][m0][n] = s0 * dm[0];
      if (m0 + 1 < TT) S.sT[hs][m0 + 1][n] = s1 * dm[1];
      if (m0 + 2 < TT) S.sT[hs][m0 + 2][n] = s2 * dm[2];
      if (m0 + 3 < TT) S.sT[hs][m0 + 3][n] = s3 * dm[3];
    }
    __syncthreads();

    // --- s@v + denom (triangular: s[n][m]=0 for n<m, skip those groups) ---
    {
      u64 ocp[9], dsp[9];
#pragma unroll
      for (int i = 0; i < 9; ++i) { ocp[i] = 0; dsp[i] = 0; }
      const float* sbase = &S.sT[hh][0][0];
#pragma unroll
      for (int m = 0; m < TT; ++m) {
        float vm = vv[m];
        u64 vmp = pk2(vm, vm);
        const float* sr = sbase + m * 20;
#pragma unroll
        for (int g = 0; g < 4; ++g) {
          if (g >= (m >> 2)) {  // groups with all n<m are exact zeros
            u64 sa, sb;
            ld128(sr + 4 * g, sa, sb);
            fma2(ocp[2 * g], sa, vmp);
            fma2(dsp[2 * g], sa, one2);
            fma2(ocp[2 * g + 1], sb, vmp);
            fma2(dsp[2 * g + 1], sb, one2);
          }
        }
        u64 s8 = ld64(sr + 16);
        fma2(ocp[8], s8, vmp);
        fma2(dsp[8], s8, one2);
      }
      float oc[18], ds[18];
#pragma unroll
      for (int i = 0; i < 9; ++i) {
        up2(ocp[i], oc[2 * i], oc[2 * i + 1]);
        up2(dsp[i], ds[2 * i], ds[2 * i + 1]);
      }
      // load raw g pairs (own row)
      float gg[18];
#pragma unroll
      for (int i = 0; i < 9; ++i)
        up2(ld64(&S.gT[d][2 * i]), gg[2 * i], gg[2 * i + 1]);
      float res[18];
#pragma unroll
      for (int n = 0; n < TT; ++n) {
        float o = oc[n] / fmaxf(fabsf(ds[n]), 1.f);
        float s1 = o, s2 = o * o;
#pragma unroll
        for (int off = 16; off; off >>= 1) {
          s1 += __shfl_xor_sync(0xffffffffu, s1, off);
          s2 += __shfl_xor_sync(0xffffffffu, s2, off);
        }
        float mu = s1 * (1.f / 32.f);
        float grs = rsqrtf(s2 * (1.f / 32.f) - mu * mu + 1e-5f);
        float sg = gg[n] / (1.f + expf(-gg[n]));
        res[n] = sg * (o - mu) * grs;
      }
      res[17] = 0.f;
      __syncthreads();
#pragma unroll
      for (int i = 0; i < 9; ++i)
        st64(&S.gT[d][2 * i], pk2(res[2 * i], res[2 * i + 1]));
    }
    __syncthreads();

    // --- output projection + residual ---
    {
      const float* Wo_ = Wo + L * VDIM * DD;
      u64 rcp[5];
#pragma unroll
      for (int i = 0; i < 5; ++i) rcp[i] = 0;
      for (int c = 0; c < VDIM; ++c) {
        float w = Wo_[c * DD + ch];
        u64 wp = pk2(w, w);
        const float* gr = &S.gT[c][tb];
        u64 g0, g1;
        ld128(gr, g0, g1);
        fma2(rcp[0], g0, wp);
        fma2(rcp[1], g1, wp);
        ld128(gr + 4, g0, g1);
        fma2(rcp[2], g0, wp);
        fma2(rcp[3], g1, wp);
        if (half) fma2(rcp[4], ld64(gr + 8), wp);  // tokens 16,17(=0)
      }
#pragma unroll
      for (int i = 0; i < 4; ++i) {
        float a, bq;
        up2(rcp[i], a, bq);
        S.h[tb + 2 * i][ch] += a;
        S.h[tb + 2 * i + 1][ch] += bq;
      }
      if (half) {
        float a, bq;
        up2(rcp[4], a, bq);
        S.h[16][ch] += a;
      }
    }
    __syncthreads();

    // --- ln2 stats (warp-parallel) ---
    ln_stats(S, d);
    __syncthreads();
    {
      float sc = ln2_s[L * DD + ch], bi = ln2_b[L * DD + ch];
      for (int i = 0; i < tc; ++i) {
        int t = tb + i;
        S.xlT[ch][t] = (S.h[t][ch] - S.mu[t]) * S.rs[t] * sc + bi;
      }
      if (half) S.xlT[ch][17] = 0.f;
    }
    __syncthreads();
    // --- FFN fc1 + gelu(tanh) ---
    for (int idx = d; idx < TT * FFND; idx += 128) {
      int n = idx / FFND, j = idx - n * FFND;
      float acc = b1[L * FFND + j];
      for (int e = 0; e < DD; ++e)
        acc += S.xlT[e][n] * w1[(L * DD + e) * FFND + j];
      float c3 = acc * acc * acc;
      S.f[n][j] = 0.5f * acc *
                  (1.f + tanhf(0.7978845608028654f * (acc + 0.044715f * c3)));
    }
    __syncthreads();
    // --- FFN fc2 + residual ---
    {
      const float* W2 = w2 + L * FFND * DD + ch;
      float bb = b2[L * DD + ch];
      u64 wj[6];
#pragma unroll
      for (int jp = 0; jp < 6; ++jp)
        wj[jp] = pk2(W2[(2 * jp) * DD], W2[(2 * jp + 1) * DD]);
      for (int i = 0; i < tc; ++i) {
        int n = tb + i;
        const float* fr = &S.f[n][0];
        u64 f0, f1, f2, f3, f4, f5;
        ld128(fr, f0, f1);
        ld128(fr + 4, f2, f3);
        ld128(fr + 8, f4, f5);
        u64 acc = 0;
        fma2(acc, f0, wj[0]);
        fma2(acc, f1, wj[1]);
        fma2(acc, f2, wj[2]);
        fma2(acc, f3, wj[3]);
        fma2(acc, f4, wj[4]);
        fma2(acc, f5, wj[5]);
        float lo, hi;
        up2(acc, lo, hi);
        S.h[n][ch] += bb + lo + hi;
      }
    }
    __syncthreads();
  }

  // ---------------- final LN (token 16) + neck + head ----------------
  if (d == 0) {
    float s1 = 0.f, s2 = 0.f;
    for (int e = 0; e < DD; e += 4) {
      float4 v = *reinterpret_cast<const float4*>(&S.h[16][e]);
      s1 += (v.x + v.y) + (v.z + v.w);
      s2 += (v.x * v.x + v.y * v.y) + (v.z * v.z + v.w * v.w);
    }
    float mu = s1 * (1.f / DD);
    S.mu[0] = mu;
    S.rs[0] = rsqrtf(s2 * (1.f / DD) - mu * mu + 1e-5f);
  }
  __syncthreads();
  if (d < 64)
    S.xlT[d][0] = (S.h[16][d] - S.mu[0]) * S.rs[0] * lnf_s[d] + lnf_b[d];
  __syncthreads();
  if (d < 16) {
    float acc = neck_b[d];
    for (int e = 0; e < DD; ++e) acc += S.xlT[e][0] * neck_w[e * 16 + d];
    S.z[d] = acc;
  }
  __syncthreads();
  if (d < 10) {
    float acc = head_b[d];
#pragma unroll
    for (int uu = 0; uu < 16; ++uu) acc += S.z[uu] * head_w[uu * 10 + d];
    out[(size_t)b * 10 + d] = acc;
  }
}

extern "C" void kernel_launch(void* const* d_in, const int* in_sizes, int n_in,
                              void* d_out, int out_size) {
  const float* x = (const float*)d_in[0];
  const float* patch_w = (const float*)d_in[1];
  const float* patch_b = (const float*)d_in[2];
  const float* cls = (const float*)d_in[3];
  const float* pos = (const float*)d_in[4];
  const float* Wq = (const float*)d_in[5];
  const float* Wk = (const float*)d_in[6];
  const float* Wv = (const float*)d_in[7];
  const float* Wg = (const float*)d_in[8];
  const float* Wo = (const float*)d_in[9];
  const float* ln1_s = (const float*)d_in[10];
  const float* ln1_b = (const float*)d_in[11];
  const float* w1 = (const float*)d_in[12];
  const float* b1 = (const float*)d_in[13];
  const float* w2 = (const float*)d_in[14];
  const float* b2 = (const float*)d_in[15];
  const float* ln2_s = (const float*)d_in[16];
  const float* ln2_b = (const float*)d_in[17];
  const float* lnf_s = (const float*)d_in[18];
  const float* lnf_b = (const float*)d_in[19];
  const float* neck_w = (const float*)d_in[20];
  const float* neck_b = (const float*)d_in[21];
  const float* head_w = (const float*)d_in[22];
  const float* head_b = (const float*)d_in[23];
  float* out = (float*)d_out;

  int B = in_sizes[0] / 3072;
  size_t smem_bytes = sizeof(SmemU);
  (void)cudaFuncSetAttribute(
      vit_kernel, cudaFuncAttributeMaxDynamicSharedMemorySize, (int)smem_bytes);

  init_tables_kernel<<<1, 1>>>();
  vit_kernel<<<B, 128, smem_bytes>>>(x, patch_w, patch_b, cls, pos, Wq, Wk, Wv,
                                     Wg, Wo, ln1_s, ln1_b, w1, b1, w2, b2,
                                     ln2_s, ln2_b, lnf_s, lnf_b, neck_w, neck_b,
                                     head_w, head_b, out);
}